// round 11
// baseline (speedup 1.0000x reference)
#include <cuda_runtime.h>
#include <cuda_bf16.h>
#include <math.h>
#include <stdint.h>

// ---------------- problem constants ----------------
#define PK      12
#define PKQ     6
#define PH      64
#define PD      768
#define DIM_MEM 768
#define DIM_MEM_TOT 780
#define DIM_CONV 1548
#define OUT_CPLX 1536
#define DIM_EXPAND 192
#define PMAXLEN 4096
#define PKSIZE  4
#define PB      4
#define PL      4096
#define NTOK    (PB*PL)
#define NCHUNK  8
#define CHROWS  (PL/NCHUNK)   // 512

// ---------------- device scratch -------------------
__device__ float g_buf0[(size_t)NTOK*DIM_CONV];   // z_pre (GEMM1 out)
__device__ float g_z   [(size_t)NTOK*DIM_CONV];   // stack -> cumsum
__device__ float g_q   [(size_t)NTOK*768];        // q channels
__device__ float g_gate[(size_t)NTOK*OUT_CPLX];
__device__ float g_csum[(size_t)PB*NCHUNK*DIM_CONV];
__device__ float g_theta[PK*PH];
__device__ float g_wint [PK*PH];
__device__ float g_slope[PK];

// bf16 split operands
__device__ __nv_bfloat16 g_xh[(size_t)NTOK*PD];
__device__ __nv_bfloat16 g_xl[(size_t)NTOK*PD];
__device__ __nv_bfloat16 g_Winh[(size_t)DIM_CONV*PD];
__device__ __nv_bfloat16 g_Winl[(size_t)DIM_CONV*PD];
__device__ __nv_bfloat16 g_Wgh[(size_t)OUT_CPLX*PD];
__device__ __nv_bfloat16 g_Wgl[(size_t)OUT_CPLX*PD];
__device__ __nv_bfloat16 g_Woh[(size_t)PD*(PK*DIM_EXPAND)];
__device__ __nv_bfloat16 g_Wol[(size_t)PD*(PK*DIM_EXPAND)];
__device__ __nv_bfloat16 g_Wrh[(size_t)PK*384*128];
__device__ __nv_bfloat16 g_Wrl[(size_t)PK*384*128];
__device__ __nv_bfloat16 g_onh[(size_t)NTOK*OUT_CPLX];
__device__ __nv_bfloat16 g_onl[(size_t)NTOK*OUT_CPLX];
__device__ __nv_bfloat16 g_yh[(size_t)NTOK*(PK*DIM_EXPAND)];
__device__ __nv_bfloat16 g_yl[(size_t)NTOK*(PK*DIM_EXPAND)];

// ---------------- helpers --------------------------
__device__ __forceinline__ float sigmoidf_(float x){ return 1.f/(1.f+expf(-x)); }
__device__ __forceinline__ float softplusf_(float x){ return (x>20.f)? x : log1pf(expf(x)); }
__device__ __forceinline__ void split2(float v, __nv_bfloat16& h, __nv_bfloat16& l){
    h = __float2bfloat16(v);
    l = __float2bfloat16(v - __bfloat162float(h));
}
__device__ __forceinline__ uint32_t smem_u32(const void* p){
    uint32_t a;
    asm("{ .reg .u64 t; cvta.to.shared.u64 t, %1; cvt.u32.u64 %0, t; }" : "=r"(a) : "l"(p));
    return a;
}
__device__ __forceinline__ void cp16(uint32_t dst, const void* src){
    asm volatile("cp.async.ca.shared.global [%0], [%1], 16;" :: "r"(dst), "l"(src));
}
template<int NG> __device__ __forceinline__ void cpwait(){
    asm volatile("cp.async.wait_group %0;" :: "n"(NG) : "memory");
}
__device__ __forceinline__ void cpcommit(){
    asm volatile("cp.async.commit_group;" ::: "memory");
}
__device__ __forceinline__ void mma16816(float* c, uint32_t a0, uint32_t a1, uint32_t a2, uint32_t a3,
                                         uint32_t b0, uint32_t b1){
    asm volatile(
        "mma.sync.aligned.m16n8k16.row.col.f32.bf16.bf16.f32 "
        "{%0,%1,%2,%3}, {%4,%5,%6,%7}, {%8,%9}, {%0,%1,%2,%3};"
        : "+f"(c[0]), "+f"(c[1]), "+f"(c[2]), "+f"(c[3])
        : "r"(a0), "r"(a1), "r"(a2), "r"(a3), "r"(b0), "r"(b1));
}
__device__ __forceinline__ void ldsm4(uint32_t& r0, uint32_t& r1, uint32_t& r2, uint32_t& r3, uint32_t addr){
    asm volatile("ldmatrix.sync.aligned.m8n8.x4.shared.b16 {%0,%1,%2,%3}, [%4];"
                 : "=r"(r0), "=r"(r1), "=r"(r2), "=r"(r3) : "r"(addr));
}

// ---------------- split-bf16 HMMA GEMM --------------
// mode 0: C fp32 store. mode 1: gated bf16-split store (val/gate interleaved cols).
#define GBM 128
#define GBN 128
#define GBK 64
#define SA  72                       // 64 elems + 8 pad (row = 144B, ldsm conflict-free)
#define TILE_ELEMS (128*SA)
#define TILE_BYTES (TILE_ELEMS*2)    // 18432
#define STAGE_BYTES (4*TILE_BYTES)   // 73728
#define NSTAGE 3
#define GSMEM (NSTAGE*STAGE_BYTES)   // 221184

__global__ void __launch_bounds__(256, 1)
gemm_mma_kernel(int M, int N, int Kd,
                const __nv_bfloat16* __restrict__ Ah, const __nv_bfloat16* __restrict__ Al,
                long long lda, long long sAb,
                const __nv_bfloat16* __restrict__ Bh, const __nv_bfloat16* __restrict__ Bl,
                long long ldb, long long sBb,
                float* __restrict__ C, long long ldc, long long sCb,
                __nv_bfloat16* __restrict__ Oh, __nv_bfloat16* __restrict__ Ol, int mode)
{
    extern __shared__ char smem[];
    const uint32_t smb = smem_u32(smem);
    const int tid = threadIdx.x;
    const int wid = tid >> 5;
    const int lid = tid & 31;
    const int g = lid >> 2;
    const int t = lid & 3;
    const int wm = (wid & 1) * 64;
    const int wn = (wid >> 1) * 32;

    const int zb = blockIdx.z;
    Ah += (long long)zb * sAb;  Al += (long long)zb * sAb;
    Bh += (long long)zb * sBb;  Bl += (long long)zb * sBb;

    const int tile_n = blockIdx.x * GBN;
    const int tile_m = blockIdx.y * GBM;
    const int nChunks = Kd / GBK;

    const int a_row  = (lid & 15);
    const int a_koff = (lid >> 4) << 3;
    const int b_row  = (lid & 7) + ((lid >> 4) << 3);
    const int b_koff = ((lid >> 3) & 1) << 3;

    float acc[4][4][4];
#pragma unroll
    for (int i = 0; i < 4; i++)
#pragma unroll
        for (int j = 0; j < 4; j++)
#pragma unroll
            for (int r = 0; r < 4; r++) acc[i][j][r] = 0.f;

    // stage loader: 4 tiles x 128 rows x 128B = 4096 cp16 chunks, 16/thread
    auto load_stage = [&](int stage, int k0){
        uint32_t sbase = smb + stage * STAGE_BYTES;
#pragma unroll
        for (int it = 0; it < 16; it++) {
            int idx = tid + it * 256;
            int tile = idx >> 10;
            int rem  = idx & 1023;
            int r    = rem >> 3;
            int seg  = rem & 7;
            uint32_t dst = sbase + tile * TILE_BYTES + r * (SA*2) + seg * 16;
            const __nv_bfloat16* src;
            if (tile == 0)      src = Ah + (long long)(tile_m + r) * lda + k0 + seg*8;
            else if (tile == 1) src = Al + (long long)(tile_m + r) * lda + k0 + seg*8;
            else {
                int n = tile_n + r;
                if (n >= N) n = 0;
                src = (tile == 2 ? Bh : Bl) + (long long)n * ldb + k0 + seg*8;
            }
            cp16(dst, src);
        }
        cpcommit();
    };

    auto compute = [&](int stage){
        const uint32_t sb = smb + stage * STAGE_BYTES;
#pragma unroll
        for (int ks = 0; ks < GBK; ks += 16) {
            uint32_t bh[4][2], bl[4][2];
#pragma unroll
            for (int p = 0; p < 2; p++) {
                uint32_t addr = sb + 2*TILE_BYTES +
                    ((wn + p*16 + b_row) * SA + ks + b_koff) * 2;
                ldsm4(bh[2*p][0], bh[2*p][1], bh[2*p+1][0], bh[2*p+1][1], addr);
                addr += TILE_BYTES;
                ldsm4(bl[2*p][0], bl[2*p][1], bl[2*p+1][0], bl[2*p+1][1], addr);
            }
#pragma unroll
            for (int mt = 0; mt < 4; mt++) {
                uint32_t ah[4], al[4];
                uint32_t addr = sb + ((wm + mt*16 + a_row) * SA + ks + a_koff) * 2;
                ldsm4(ah[0], ah[1], ah[2], ah[3], addr);
                ldsm4(al[0], al[1], al[2], al[3], addr + TILE_BYTES);
#pragma unroll
                for (int nt = 0; nt < 4; nt++)
                    mma16816(acc[mt][nt], ah[0], ah[1], ah[2], ah[3], bh[nt][0], bh[nt][1]);
#pragma unroll
                for (int nt = 0; nt < 4; nt++)
                    mma16816(acc[mt][nt], al[0], al[1], al[2], al[3], bh[nt][0], bh[nt][1]);
#pragma unroll
                for (int nt = 0; nt < 4; nt++)
                    mma16816(acc[mt][nt], ah[0], ah[1], ah[2], ah[3], bl[nt][0], bl[nt][1]);
            }
        }
    };

    load_stage(0, 0);
    if (nChunks > 1) load_stage(1, GBK);
    for (int i = 0; i < nChunks; i++) {
        if (i == nChunks - 1) cpwait<0>(); else cpwait<1>();
        __syncthreads();
        if (i + 2 < nChunks) load_stage((i + 2) % NSTAGE, (i + 2) * GBK);
        compute(i % NSTAGE);
        // no trailing sync: 3-stage ring + top-of-loop barrier protects reuse
    }

    if (mode == 0) {
        float* Cz = C + (long long)zb * sCb;
#pragma unroll
        for (int mt = 0; mt < 4; mt++) {
            int row0 = tile_m + wm + mt*16 + g;
#pragma unroll
            for (int nt = 0; nt < 4; nt++) {
                int col = tile_n + wn + nt*8 + 2*t;
                if (col < N) {
                    float* p0 = Cz + (long long)row0 * ldc + col;
                    float* p1 = Cz + (long long)(row0 + 8) * ldc + col;
                    p0[0] = acc[mt][nt][0]; p0[1] = acc[mt][nt][1];
                    p1[0] = acc[mt][nt][2]; p1[1] = acc[mt][nt][3];
                }
            }
        }
    } else {
        // interleaved val/gate pairs: even col = val, odd col = gate
        const long long ldo = PK * DIM_EXPAND;   // 2304
        const long long ob = (long long)zb * DIM_EXPAND;
#pragma unroll
        for (int mt = 0; mt < 4; mt++) {
            int row0 = tile_m + wm + mt*16 + g;
#pragma unroll
            for (int nt = 0; nt < 4; nt++) {
                int col = tile_n + wn + nt*8 + 2*t;   // even
                int n_out = col >> 1;
                float r0 = acc[mt][nt][0] * sigmoidf_(acc[mt][nt][1]);
                float r1 = acc[mt][nt][2] * sigmoidf_(acc[mt][nt][3]);
                __nv_bfloat16 h0, l0, h1, l1;
                split2(r0, h0, l0); split2(r1, h1, l1);
                long long o0 = (long long)row0 * ldo + ob + n_out;
                long long o1 = (long long)(row0 + 8) * ldo + ob + n_out;
                Oh[o0] = h0; Ol[o0] = l0;
                Oh[o1] = h1; Ol[o1] = l1;
            }
        }
    }
}

// ---------------- conversion kernels ----------------
__global__ void split_x_kernel(const float* __restrict__ x)
{
    size_t i = (size_t)blockIdx.x * blockDim.x + threadIdx.x;
    if (i >= (size_t)NTOK * PD) return;
    split2(x[i], g_xh[i], g_xl[i]);
}

// W[K,N] -> out[N,K] hi/lo via 32x32 smem tile transpose
__global__ void tsplit_kernel(const float* __restrict__ W,
                              __nv_bfloat16* __restrict__ oh,
                              __nv_bfloat16* __restrict__ ol,
                              int K, int N)
{
    __shared__ float tile[32][33];
    int n0 = blockIdx.x * 32, k0 = blockIdx.y * 32;
    int tx = threadIdx.x, ty = threadIdx.y;
#pragma unroll
    for (int i = ty; i < 32; i += 8) {
        int n = n0 + tx;
        tile[i][tx] = (n < N) ? W[(size_t)(k0 + i) * N + n] : 0.f;
    }
    __syncthreads();
#pragma unroll
    for (int i = ty; i < 32; i += 8) {
        int n = n0 + i;
        if (n < N) {
            __nv_bfloat16 h, l;
            split2(tile[tx][i], h, l);
            size_t o = (size_t)n * K + k0 + tx;
            oh[o] = h; ol[o] = l;
        }
    }
}

// W_read[12][128][384] -> Wr[12][n'][128], n' = interleave(val j -> 2j, gate j -> 2j+1)
__global__ void tsplit_wr_kernel(const float* __restrict__ W)
{
    int i = blockIdx.x * blockDim.x + threadIdx.x;
    if (i >= PK * 128 * 384) return;
    int b = i / (128 * 384);
    int rem = i - b * 128 * 384;
    int f = rem / 384, n = rem - f * 384;
    int np = (n < DIM_EXPAND) ? (2*n) : (2*(n - DIM_EXPAND) + 1);
    __nv_bfloat16 h, l;
    split2(W[i], h, l);
    size_t o = (size_t)b * 384 * 128 + (size_t)np * 128 + f;
    g_Wrh[o] = h; g_Wrl[o] = l;
}

// ---------------- small precompute ------------------
__global__ void prep_kernel(const float* __restrict__ theta_raw,
                            const float* __restrict__ wint_raw,
                            const float* __restrict__ decay)
{
    int i = threadIdx.x;
    if (i < PK*PH) {
        g_theta[i] = 0.001f + 2.999f * sigmoidf_(theta_raw[i]);
        float e = expf(wint_raw[i]);
        g_wint[i] = e / (e + 1e-6f);
    }
    if (i < PK) g_slope[i] = softplusf_(decay[i]);
}

// ---------------- fused conv+silu+stack, 8 tokens/block with smem row cache
#define TT 8
#define ROWS_S (TT + 3)   // 11
#define CS_SMEM ((ROWS_S*DIM_CONV + TT*PK) * 4)   // 68496 B

__global__ void __launch_bounds__(256)
convstack_kernel(const float* __restrict__ conv_w,
                 const float* __restrict__ score_scale,
                 const float* __restrict__ score_bias,
                 const float* __restrict__ phase_scale)
{
    extern __shared__ float sm[];
    float* rows = sm;                       // [11][1548]
    float* spw  = sm + ROWS_S*DIM_CONV;     // [TT][PK]
    int tid = threadIdx.x;
    int tok0 = blockIdx.x * TT;
    int l0 = tok0 & (PL-1);
    long long bbase = (long long)(tok0 - l0) * DIM_CONV;  // batch start

    // load 11 rows (l0-3 .. l0+7), zero-fill before batch start
    for (int idx = tid; idx < ROWS_S * (DIM_CONV/4); idx += 256) {
        int rr = idx / (DIM_CONV/4);
        int c4 = (idx - rr * (DIM_CONV/4)) * 4;
        int l = l0 - 3 + rr;
        float4 v = make_float4(0.f, 0.f, 0.f, 0.f);
        if (l >= 0) v = *(const float4*)&g_buf0[bbase + (long long)l * DIM_CONV + c4];
        *(float4*)&rows[rr*DIM_CONV + c4] = v;
    }
    __syncthreads();

    // p_w for the 8 tokens (96 threads)
    if (tid < TT*PK) {
        int t = tid / PK, k = tid - (tid/PK)*PK;
        int c = DIM_MEM + k;
        float a = 0.f;
#pragma unroll
        for (int tt = 0; tt < PKSIZE; tt++)
            a += rows[(t + tt)*DIM_CONV + c] * conv_w[tt*DIM_CONV + c];
        float s = a * sigmoidf_(a);
        float u  = score_scale[k]*s + score_bias[k];
        float sp = softplusf_(u);
        float tw = expf(-g_slope[k] * (float)(PMAXLEN-1 - (l0 + t)));
        float p  = fminf(fmaxf(sp*tw, 1e-4f), 5000.f);
        spw[tid] = p;
        g_z[(long long)(tok0 + t) * DIM_CONV + k] = p;
    }
    __syncthreads();

    // re/im channels: 8 tokens x 768
    for (int idx = tid; idx < TT*DIM_MEM; idx += 256) {
        int t = idx / DIM_MEM;
        int i = idx - t*DIM_MEM;
        int k = i >> 6;
        float a = 0.f;
#pragma unroll
        for (int tt = 0; tt < PKSIZE; tt++)
            a += rows[(t + tt)*DIM_CONV + i] * conv_w[tt*DIM_CONV + i];
        float kv = a * sigmoidf_(a);
        float ks = kv * phase_scale[k];
        float phi = ks / (1.f + fabsf(ks)) * g_theta[i];
        float sn, cs;
        sincosf(phi, &sn, &cs);
        float kvw = kv * spw[t*PK + k];
        long long zr = (long long)(tok0 + t) * DIM_CONV;
        g_z[zr + PK + i]           = kvw * cs;
        g_z[zr + PK + DIM_MEM + i] = kvw * sn;
    }

    // q channels: 8 tokens x 768
    for (int idx = tid; idx < TT*768; idx += 256) {
        int t = idx / 768;
        int i = idx - t*768;
        int c = DIM_MEM_TOT + i;
        float a = 0.f;
#pragma unroll
        for (int tt = 0; tt < PKSIZE; tt++)
            a += rows[(t + tt)*DIM_CONV + c] * conv_w[tt*DIM_CONV + c];
        g_q[(long long)(tok0 + t) * 768 + i] = a * sigmoidf_(a);
    }
}

// ---------------- chunked scan (over g_z) -----------
__global__ void scan_partial_kernel()
{
    int c = blockIdx.x * blockDim.x + threadIdx.x;
    if (c >= DIM_CONV) return;
    int chunk = blockIdx.y;
    int b = blockIdx.z;

    long long base = ((long long)(b*PL + chunk*CHROWS)) * DIM_CONV + c;
    float run = 0.f;
#pragma unroll 4
    for (int r = 0; r < CHROWS; r++) {
        long long p = base + (long long)r * DIM_CONV;
        run += g_z[p];
        g_z[p] = run;
    }
    g_csum[((long long)(b*NCHUNK + chunk))*DIM_CONV + c] = run;
}

__global__ void scan_offsets_kernel()
{
    int i = blockIdx.x * blockDim.x + threadIdx.x;
    if (i >= PB*DIM_CONV) return;
    int b = i / DIM_CONV;
    int c = i - b*DIM_CONV;
    float off = 0.f;
#pragma unroll
    for (int ch = 0; ch < NCHUNK; ch++) {
        long long idx = ((long long)(b*NCHUNK + ch))*DIM_CONV + c;
        float t = g_csum[idx];
        g_csum[idx] = off;
        off += t;
    }
}

// ---------------- epilogue 1 ------------------------
__global__ void epilogue1_kernel(const float* __restrict__ gnw)
{
    __shared__ float s_inv[PK];
    __shared__ float s_red[8];
    int tok = blockIdx.x;
    int tid = threadIdx.x;
    int l = tok & (PL-1);
    int b = tok >> 12;
    int chunk = l >> 9;   // l / CHROWS(512)

    long long zb  = (long long)tok * DIM_CONV;
    long long ob  = ((long long)(b*NCHUNK + chunk)) * DIM_CONV;
    long long gb  = (long long)tok * OUT_CPLX;
    long long qb  = (long long)tok * 768;

    if (tid < PK) {
        float den = g_z[zb + tid] + g_csum[ob + tid];
        s_inv[tid] = 1.f / fmaxf(den, 1e-4f);
    }
    __syncthreads();

    float hvals[OUT_CPLX/256];
    float sumsq = 0.f;
#pragma unroll
    for (int it = 0; it < OUT_CPLX/256; it++) {
        int f = tid + it*256;
        int k = f >> 7;
        int j = f & 127;
        int h = j & 63;
        int is_im = j >> 6;
        int idx = k*PH + h;

        float re_acc = g_z[zb + PK + idx]           + g_csum[ob + PK + idx];
        float im_acc = g_z[zb + PK + DIM_MEM + idx] + g_csum[ob + PK + DIM_MEM + idx];
        float sre = re_acc * s_inv[k];
        float sim = im_acc * s_inv[k];
        int kq = k >> 1;
        float qre = g_q[qb + (kq*PH + h)*2];
        float qim = g_q[qb + (kq*PH + h)*2 + 1];
        float val;
        if (!is_im) val = (sre*qre + sim*qim);
        else        val = (sim*qre - sre*qim);
        val *= 0.125f * g_wint[idx];

        float gv = g_gate[gb + f];
        float hv = val * (gv * sigmoidf_(gv));
        hvals[it] = hv;
        sumsq += hv*hv;
    }
#pragma unroll
    for (int o = 16; o > 0; o >>= 1) sumsq += __shfl_xor_sync(0xffffffff, sumsq, o);
    if ((tid & 31) == 0) s_red[tid >> 5] = sumsq;
    __syncthreads();
    if (tid < 32) {
        float v = (tid < 8) ? s_red[tid] : 0.f;
#pragma unroll
        for (int o = 4; o > 0; o >>= 1) v += __shfl_xor_sync(0xffffffff, v, o);
        if (tid == 0) s_red[0] = v;
    }
    __syncthreads();
    float rms = rsqrtf(s_red[0] / (float)OUT_CPLX + 1e-6f);

#pragma unroll
    for (int it = 0; it < OUT_CPLX/256; it++) {
        int f = tid + it*256;
        float v = hvals[it] * rms * gnw[f];
        __nv_bfloat16 h, lo;
        split2(v, h, lo);
        g_onh[gb + f] = h;
        g_onl[gb + f] = lo;
    }
}

// ---------------- launcher --------------------------
extern "C" void kernel_launch(void* const* d_in, const int* in_sizes, int n_in,
                              void* d_out, int out_size)
{
    const float* x        = (const float*)d_in[0];
    const float* W_in     = (const float*)d_in[1];
    const float* conv_w   = (const float*)d_in[2];
    const float* theta_raw= (const float*)d_in[3];
    const float* wint_raw = (const float*)d_in[4];
    const float* decay    = (const float*)d_in[5];
    const float* sscale   = (const float*)d_in[6];
    const float* sbias    = (const float*)d_in[7];
    const float* pscale   = (const float*)d_in[8];
    const float* gnw      = (const float*)d_in[9];
    const float* W_read   = (const float*)d_in[10];
    const float* W_gate   = (const float*)d_in[11];
    const float* W_out    = (const float*)d_in[12];
    float* out            = (float*)d_out;

    float *p_buf0, *p_gate;
    __nv_bfloat16 *p_xh, *p_xl, *p_Winh, *p_Winl, *p_Wgh, *p_Wgl;
    __nv_bfloat16 *p_Woh, *p_Wol, *p_Wrh, *p_Wrl, *p_onh, *p_onl, *p_yh, *p_yl;
    cudaGetSymbolAddress((void**)&p_buf0, g_buf0);
    cudaGetSymbolAddress((void**)&p_gate, g_gate);
    cudaGetSymbolAddress((void**)&p_xh,   g_xh);
    cudaGetSymbolAddress((void**)&p_xl,   g_xl);
    cudaGetSymbolAddress((void**)&p_Winh, g_Winh);
    cudaGetSymbolAddress((void**)&p_Winl, g_Winl);
    cudaGetSymbolAddress((void**)&p_Wgh,  g_Wgh);
    cudaGetSymbolAddress((void**)&p_Wgl,  g_Wgl);
    cudaGetSymbolAddress((void**)&p_Woh,  g_Woh);
    cudaGetSymbolAddress((void**)&p_Wol,  g_Wol);
    cudaGetSymbolAddress((void**)&p_Wrh,  g_Wrh);
    cudaGetSymbolAddress((void**)&p_Wrl,  g_Wrl);
    cudaGetSymbolAddress((void**)&p_onh,  g_onh);
    cudaGetSymbolAddress((void**)&p_onl,  g_onl);
    cudaGetSymbolAddress((void**)&p_yh,   g_yh);
    cudaGetSymbolAddress((void**)&p_yl,   g_yl);

    cudaFuncSetAttribute(gemm_mma_kernel,
                         cudaFuncAttributeMaxDynamicSharedMemorySize, GSMEM);
    cudaFuncSetAttribute(convstack_kernel,
                         cudaFuncAttributeMaxDynamicSharedMemorySize, CS_SMEM);

    // 0) precompute + conversions
    prep_kernel<<<1, 768>>>(theta_raw, wint_raw, decay);
    {
        size_t n = (size_t)NTOK * PD;
        split_x_kernel<<<(unsigned)((n + 255) / 256), 256>>>(x);
    }
    {
        dim3 blk(32, 8);
        tsplit_kernel<<<dim3((DIM_CONV+31)/32, PD/32),  blk>>>(W_in,  p_Winh, p_Winl, PD, DIM_CONV);
        tsplit_kernel<<<dim3(OUT_CPLX/32,      PD/32),  blk>>>(W_gate, p_Wgh, p_Wgl, PD, OUT_CPLX);
        tsplit_kernel<<<dim3(PD/32,          2304/32),  blk>>>(W_out, p_Woh, p_Wol, 2304, PD);
    }
    tsplit_wr_kernel<<<(PK*128*384 + 255)/256, 256>>>(W_read);

    // 1) z_pre = x @ W_in
    gemm_mma_kernel<<<dim3((DIM_CONV + GBN - 1)/GBN, NTOK/GBM, 1), 256, GSMEM>>>(
        NTOK, DIM_CONV, PD, p_xh, p_xl, PD, 0, p_Winh, p_Winl, PD, 0,
        p_buf0, DIM_CONV, 0, nullptr, nullptr, 0);

    // 2) fused conv+silu+stack, 8 tokens/block with smem cache
    convstack_kernel<<<NTOK/TT, 256, CS_SMEM>>>(conv_w, sscale, sbias, pscale);

    // 3) chunked cumsum over g_z
    scan_partial_kernel<<<dim3((DIM_CONV+127)/128, NCHUNK, PB), 128>>>();
    scan_offsets_kernel<<<(PB*DIM_CONV+255)/256, 256>>>();

    // 4) gate = x @ W_gate
    gemm_mma_kernel<<<dim3(OUT_CPLX/GBN, NTOK/GBM, 1), 256, GSMEM>>>(
        NTOK, OUT_CPLX, PD, p_xh, p_xl, PD, 0, p_Wgh, p_Wgl, PD, 0,
        p_gate, OUT_CPLX, 0, nullptr, nullptr, 0);

    // 5) epilogue: out_flat + gated rmsnorm -> bf16 split
    epilogue1_kernel<<<NTOK, 256>>>(gnw);

    // 6) batched readout + fused gating (12 batches) -> g_yh/g_yl
    gemm_mma_kernel<<<dim3(384/GBN, NTOK/GBM, PK), 256, GSMEM>>>(
        NTOK, 384, 128,
        p_onh, p_onl, OUT_CPLX, 128,
        p_Wrh, p_Wrl, 128, (long long)384*128,
        nullptr, 0, 0, p_yh, p_yl, 1);

    // 7) final: out = y @ W_out
    gemm_mma_kernel<<<dim3(PD/GBN, NTOK/GBM, 1), 256, GSMEM>>>(
        NTOK, PD, PK*DIM_EXPAND, p_yh, p_yl, PK*DIM_EXPAND, 0,
        p_Woh, p_Wol, PK*DIM_EXPAND, 0, out, PD, 0, nullptr, nullptr, 0);
}

// round 12
// speedup vs baseline: 1.0698x; 1.0698x over previous
#include <cuda_runtime.h>
#include <cuda_bf16.h>
#include <math.h>
#include <stdint.h>

// ---------------- problem constants ----------------
#define PK      12
#define PKQ     6
#define PH      64
#define PD      768
#define DIM_MEM 768
#define DIM_MEM_TOT 780
#define DIM_CONV 1548
#define OUT_CPLX 1536
#define DIM_EXPAND 192
#define PMAXLEN 4096
#define PKSIZE  4
#define PB      4
#define PL      4096
#define NTOK    (PB*PL)
#define NCHUNK  8
#define CHROWS  (PL/NCHUNK)   // 512

// ---------------- device scratch -------------------
__device__ float g_buf0[(size_t)NTOK*DIM_CONV];   // z_pre (GEMM1 out)
__device__ float g_z   [(size_t)NTOK*DIM_CONV];   // stack -> cumsum
__device__ float g_q   [(size_t)NTOK*768];        // q channels
__device__ float g_gate[(size_t)NTOK*OUT_CPLX];
__device__ float g_csum[(size_t)PB*NCHUNK*DIM_CONV];
__device__ float g_theta[PK*PH];
__device__ float g_wint [PK*PH];
__device__ float g_slope[PK];

// bf16 split operands
__device__ __nv_bfloat16 g_xh[(size_t)NTOK*PD];
__device__ __nv_bfloat16 g_xl[(size_t)NTOK*PD];
__device__ __nv_bfloat16 g_Winh[(size_t)DIM_CONV*PD];
__device__ __nv_bfloat16 g_Winl[(size_t)DIM_CONV*PD];
__device__ __nv_bfloat16 g_Wgh[(size_t)OUT_CPLX*PD];
__device__ __nv_bfloat16 g_Wgl[(size_t)OUT_CPLX*PD];
__device__ __nv_bfloat16 g_Woh[(size_t)PD*(PK*DIM_EXPAND)];
__device__ __nv_bfloat16 g_Wol[(size_t)PD*(PK*DIM_EXPAND)];
__device__ __nv_bfloat16 g_Wrh[(size_t)PK*384*128];
__device__ __nv_bfloat16 g_Wrl[(size_t)PK*384*128];
__device__ __nv_bfloat16 g_onh[(size_t)NTOK*OUT_CPLX];
__device__ __nv_bfloat16 g_onl[(size_t)NTOK*OUT_CPLX];
__device__ __nv_bfloat16 g_yh[(size_t)NTOK*(PK*DIM_EXPAND)];
__device__ __nv_bfloat16 g_yl[(size_t)NTOK*(PK*DIM_EXPAND)];

// ---------------- helpers --------------------------
__device__ __forceinline__ float sigmoidf_(float x){ return 1.f/(1.f+expf(-x)); }
__device__ __forceinline__ float softplusf_(float x){ return (x>20.f)? x : log1pf(expf(x)); }
__device__ __forceinline__ void split2(float v, __nv_bfloat16& h, __nv_bfloat16& l){
    h = __float2bfloat16(v);
    l = __float2bfloat16(v - __bfloat162float(h));
}
__device__ __forceinline__ uint32_t smem_u32(const void* p){
    uint32_t a;
    asm("{ .reg .u64 t; cvta.to.shared.u64 t, %1; cvt.u32.u64 %0, t; }" : "=r"(a) : "l"(p));
    return a;
}
__device__ __forceinline__ void cp16(uint32_t dst, const void* src){
    asm volatile("cp.async.ca.shared.global [%0], [%1], 16;" :: "r"(dst), "l"(src));
}
template<int NG> __device__ __forceinline__ void cpwait(){
    asm volatile("cp.async.wait_group %0;" :: "n"(NG) : "memory");
}
__device__ __forceinline__ void cpcommit(){
    asm volatile("cp.async.commit_group;" ::: "memory");
}
__device__ __forceinline__ void mma16816(float* c, uint32_t a0, uint32_t a1, uint32_t a2, uint32_t a3,
                                         uint32_t b0, uint32_t b1){
    asm volatile(
        "mma.sync.aligned.m16n8k16.row.col.f32.bf16.bf16.f32 "
        "{%0,%1,%2,%3}, {%4,%5,%6,%7}, {%8,%9}, {%0,%1,%2,%3};"
        : "+f"(c[0]), "+f"(c[1]), "+f"(c[2]), "+f"(c[3])
        : "r"(a0), "r"(a1), "r"(a2), "r"(a3), "r"(b0), "r"(b1));
}
__device__ __forceinline__ void ldsm4(uint32_t& r0, uint32_t& r1, uint32_t& r2, uint32_t& r3, uint32_t addr){
    asm volatile("ldmatrix.sync.aligned.m8n8.x4.shared.b16 {%0,%1,%2,%3}, [%4];"
                 : "=r"(r0), "=r"(r1), "=r"(r2), "=r"(r3) : "r"(addr));
}

// ---------------- split-bf16 HMMA GEMM --------------
// mode 0: C fp32 store. mode 1: gated bf16-split store (val/gate interleaved cols).
#define GBM 128
#define GBN 128
#define GBK 32
#define SA  40
#define TILE_ELEMS (128*SA)
#define TILE_BYTES (TILE_ELEMS*2)
#define STAGE_BYTES (4*TILE_BYTES)
#define NSTAGE 3
#define GSMEM (NSTAGE*STAGE_BYTES)

__global__ void __launch_bounds__(256, 1)
gemm_mma_kernel(int M, int N, int Kd,
                const __nv_bfloat16* __restrict__ Ah, const __nv_bfloat16* __restrict__ Al,
                long long lda, long long sAb,
                const __nv_bfloat16* __restrict__ Bh, const __nv_bfloat16* __restrict__ Bl,
                long long ldb, long long sBb,
                float* __restrict__ C, long long ldc, long long sCb,
                __nv_bfloat16* __restrict__ Oh, __nv_bfloat16* __restrict__ Ol, int mode)
{
    extern __shared__ char smem[];
    const uint32_t smb = smem_u32(smem);
    const int tid = threadIdx.x;
    const int wid = tid >> 5;
    const int lid = tid & 31;
    const int g = lid >> 2;
    const int t = lid & 3;
    const int wm = (wid & 1) * 64;
    const int wn = (wid >> 1) * 32;

    const int zb = blockIdx.z;
    Ah += (long long)zb * sAb;  Al += (long long)zb * sAb;
    Bh += (long long)zb * sBb;  Bl += (long long)zb * sBb;

    const int tile_n = blockIdx.x * GBN;
    const int tile_m = blockIdx.y * GBM;
    const int nChunks = Kd / GBK;

    const int a_row  = (lid & 15);
    const int a_koff = (lid >> 4) << 3;
    const int b_row  = (lid & 7) + ((lid >> 4) << 3);
    const int b_koff = ((lid >> 3) & 1) << 3;

    float acc[4][4][4];
#pragma unroll
    for (int i = 0; i < 4; i++)
#pragma unroll
        for (int j = 0; j < 4; j++)
#pragma unroll
            for (int r = 0; r < 4; r++) acc[i][j][r] = 0.f;

    auto load_stage = [&](int stage, int k0){
        uint32_t sbase = smb + stage * STAGE_BYTES;
#pragma unroll
        for (int it = 0; it < 8; it++) {
            int idx = tid + it * 256;
            int tile = idx >> 9;
            int r    = (idx >> 2) & 127;
            int seg  = idx & 3;
            uint32_t dst = sbase + tile * TILE_BYTES + r * (SA*2) + seg * 16;
            const __nv_bfloat16* src;
            if (tile == 0)      src = Ah + (long long)(tile_m + r) * lda + k0 + seg*8;
            else if (tile == 1) src = Al + (long long)(tile_m + r) * lda + k0 + seg*8;
            else {
                int n = tile_n + r;
                if (n >= N) n = 0;
                src = (tile == 2 ? Bh : Bl) + (long long)n * ldb + k0 + seg*8;
            }
            cp16(dst, src);
        }
        cpcommit();
    };

    auto compute = [&](int stage){
        const uint32_t sb = smb + stage * STAGE_BYTES;
#pragma unroll
        for (int ks = 0; ks < GBK; ks += 16) {
            uint32_t bh[4][2], bl[4][2];
#pragma unroll
            for (int p = 0; p < 2; p++) {
                uint32_t addr = sb + 2*TILE_BYTES +
                    ((wn + p*16 + b_row) * SA + ks + b_koff) * 2;
                ldsm4(bh[2*p][0], bh[2*p][1], bh[2*p+1][0], bh[2*p+1][1], addr);
                addr += TILE_BYTES;
                ldsm4(bl[2*p][0], bl[2*p][1], bl[2*p+1][0], bl[2*p+1][1], addr);
            }
#pragma unroll
            for (int mt = 0; mt < 4; mt++) {
                uint32_t ah[4], al[4];
                uint32_t addr = sb + ((wm + mt*16 + a_row) * SA + ks + a_koff) * 2;
                ldsm4(ah[0], ah[1], ah[2], ah[3], addr);
                ldsm4(al[0], al[1], al[2], al[3], addr + TILE_BYTES);
#pragma unroll
                for (int nt = 0; nt < 4; nt++)
                    mma16816(acc[mt][nt], ah[0], ah[1], ah[2], ah[3], bh[nt][0], bh[nt][1]);
#pragma unroll
                for (int nt = 0; nt < 4; nt++)
                    mma16816(acc[mt][nt], al[0], al[1], al[2], al[3], bh[nt][0], bh[nt][1]);
#pragma unroll
                for (int nt = 0; nt < 4; nt++)
                    mma16816(acc[mt][nt], ah[0], ah[1], ah[2], ah[3], bl[nt][0], bl[nt][1]);
            }
        }
    };

    load_stage(0, 0);
    if (nChunks > 1) load_stage(1, GBK);
    for (int i = 0; i < nChunks; i++) {
        if (i == nChunks - 1) cpwait<0>(); else cpwait<1>();
        __syncthreads();
        if (i + 2 < nChunks) load_stage((i + 2) % NSTAGE, (i + 2) * GBK);
        compute(i % NSTAGE);
        // no trailing sync: 3-stage ring + top-of-loop barrier protects reuse
    }

    if (mode == 0) {
        float* Cz = C + (long long)zb * sCb;
#pragma unroll
        for (int mt = 0; mt < 4; mt++) {
            int row0 = tile_m + wm + mt*16 + g;
#pragma unroll
            for (int nt = 0; nt < 4; nt++) {
                int col = tile_n + wn + nt*8 + 2*t;
                if (col < N) {
                    float* p0 = Cz + (long long)row0 * ldc + col;
                    float* p1 = Cz + (long long)(row0 + 8) * ldc + col;
                    p0[0] = acc[mt][nt][0]; p0[1] = acc[mt][nt][1];
                    p1[0] = acc[mt][nt][2]; p1[1] = acc[mt][nt][3];
                }
            }
        }
    } else {
        // interleaved val/gate pairs: even col = val, odd col = gate
        const long long ldo = PK * DIM_EXPAND;   // 2304
        const long long ob = (long long)zb * DIM_EXPAND;
#pragma unroll
        for (int mt = 0; mt < 4; mt++) {
            int row0 = tile_m + wm + mt*16 + g;
#pragma unroll
            for (int nt = 0; nt < 4; nt++) {
                int col = tile_n + wn + nt*8 + 2*t;   // even
                int n_out = col >> 1;
                float r0 = acc[mt][nt][0] * sigmoidf_(acc[mt][nt][1]);
                float r1 = acc[mt][nt][2] * sigmoidf_(acc[mt][nt][3]);
                __nv_bfloat16 h0, l0, h1, l1;
                split2(r0, h0, l0); split2(r1, h1, l1);
                long long o0 = (long long)row0 * ldo + ob + n_out;
                long long o1 = (long long)(row0 + 8) * ldo + ob + n_out;
                Oh[o0] = h0; Ol[o0] = l0;
                Oh[o1] = h1; Ol[o1] = l1;
            }
        }
    }
}

// ---------------- conversion kernels ----------------
__global__ void split_x_kernel(const float* __restrict__ x)
{
    size_t i = (size_t)blockIdx.x * blockDim.x + threadIdx.x;
    if (i >= (size_t)NTOK * PD) return;
    split2(x[i], g_xh[i], g_xl[i]);
}

// W[K,N] -> out[N,K] hi/lo via 32x32 smem tile transpose
__global__ void tsplit_kernel(const float* __restrict__ W,
                              __nv_bfloat16* __restrict__ oh,
                              __nv_bfloat16* __restrict__ ol,
                              int K, int N)
{
    __shared__ float tile[32][33];
    int n0 = blockIdx.x * 32, k0 = blockIdx.y * 32;
    int tx = threadIdx.x, ty = threadIdx.y;
#pragma unroll
    for (int i = ty; i < 32; i += 8) {
        int n = n0 + tx;
        tile[i][tx] = (n < N) ? W[(size_t)(k0 + i) * N + n] : 0.f;
    }
    __syncthreads();
#pragma unroll
    for (int i = ty; i < 32; i += 8) {
        int n = n0 + i;
        if (n < N) {
            __nv_bfloat16 h, l;
            split2(tile[tx][i], h, l);
            size_t o = (size_t)n * K + k0 + tx;
            oh[o] = h; ol[o] = l;
        }
    }
}

// W_read[12][128][384] -> Wr[12][n'][128], n' = interleave(val j -> 2j, gate j -> 2j+1)
__global__ void tsplit_wr_kernel(const float* __restrict__ W)
{
    int i = blockIdx.x * blockDim.x + threadIdx.x;
    if (i >= PK * 128 * 384) return;
    int b = i / (128 * 384);
    int rem = i - b * 128 * 384;
    int f = rem / 384, n = rem - f * 384;
    int np = (n < DIM_EXPAND) ? (2*n) : (2*(n - DIM_EXPAND) + 1);
    __nv_bfloat16 h, l;
    split2(W[i], h, l);
    size_t o = (size_t)b * 384 * 128 + (size_t)np * 128 + f;
    g_Wrh[o] = h; g_Wrl[o] = l;
}

// ---------------- small precompute ------------------
__global__ void prep_kernel(const float* __restrict__ theta_raw,
                            const float* __restrict__ wint_raw,
                            const float* __restrict__ decay)
{
    int i = threadIdx.x;
    if (i < PK*PH) {
        g_theta[i] = 0.001f + 2.999f * sigmoidf_(theta_raw[i]);
        float e = expf(wint_raw[i]);
        g_wint[i] = e / (e + 1e-6f);
    }
    if (i < PK) g_slope[i] = softplusf_(decay[i]);
}

// ---------------- fused conv+silu+stack -------------
// reads z_pre (g_buf0), writes stack -> g_z, q -> g_q
__global__ void convstack_kernel(const float* __restrict__ conv_w,
                                 const float* __restrict__ score_scale,
                                 const float* __restrict__ score_bias,
                                 const float* __restrict__ phase_scale)
{
    __shared__ float s_pw[PK];
    int tok = blockIdx.x;
    int tid = threadIdx.x;
    int l = tok & (PL-1);
    long long zb = (long long)tok * DIM_CONV;

    auto conv1 = [&](int c) -> float {
        float acc = 0.f;
#pragma unroll
        for (int tt = 0; tt < PKSIZE; tt++) {
            int dl = l + tt - (PKSIZE-1);
            if (dl >= 0)
                acc += g_buf0[zb + (long long)(tt - (PKSIZE-1)) * DIM_CONV + c]
                       * conv_w[tt*DIM_CONV + c];
        }
        return acc * sigmoidf_(acc);
    };

    if (tid < PK) {
        float s  = conv1(DIM_MEM + tid);
        float u  = score_scale[tid]*s + score_bias[tid];
        float sp = softplusf_(u);
        float tw = expf(-g_slope[tid] * (float)(PMAXLEN-1 - l));
        float p  = fminf(fmaxf(sp*tw, 1e-4f), 5000.f);
        s_pw[tid] = p;
        g_z[zb + tid] = p;
    }
    __syncthreads();

    for (int i = tid; i < DIM_MEM; i += blockDim.x) {
        int k = i >> 6;
        float kv = conv1(i);
        float ks = kv * phase_scale[k];
        float phi = ks / (1.f + fabsf(ks)) * g_theta[i];
        float sn, cs;
        sincosf(phi, &sn, &cs);
        float kvw = kv * s_pw[k];
        g_z[zb + PK + i]           = kvw * cs;
        g_z[zb + PK + DIM_MEM + i] = kvw * sn;
    }
    for (int i = tid; i < 768; i += blockDim.x) {
        g_q[(long long)tok * 768 + i] = conv1(DIM_MEM_TOT + i);
    }
}

// ---------------- chunked scan (over g_z) -----------
__global__ void scan_partial_kernel()
{
    int c = blockIdx.x * blockDim.x + threadIdx.x;
    if (c >= DIM_CONV) return;
    int chunk = blockIdx.y;
    int b = blockIdx.z;

    long long base = ((long long)(b*PL + chunk*CHROWS)) * DIM_CONV + c;
    float run = 0.f;
#pragma unroll 4
    for (int r = 0; r < CHROWS; r++) {
        long long p = base + (long long)r * DIM_CONV;
        run += g_z[p];
        g_z[p] = run;
    }
    g_csum[((long long)(b*NCHUNK + chunk))*DIM_CONV + c] = run;
}

__global__ void scan_offsets_kernel()
{
    int i = blockIdx.x * blockDim.x + threadIdx.x;
    if (i >= PB*DIM_CONV) return;
    int b = i / DIM_CONV;
    int c = i - b*DIM_CONV;
    float off = 0.f;
#pragma unroll
    for (int ch = 0; ch < NCHUNK; ch++) {
        long long idx = ((long long)(b*NCHUNK + ch))*DIM_CONV + c;
        float t = g_csum[idx];
        g_csum[idx] = off;
        off += t;
    }
}

// ---------------- epilogue 1 ------------------------
__global__ void epilogue1_kernel(const float* __restrict__ gnw)
{
    __shared__ float s_inv[PK];
    __shared__ float s_red[8];
    int tok = blockIdx.x;
    int tid = threadIdx.x;
    int l = tok & (PL-1);
    int b = tok >> 12;
    int chunk = l >> 9;   // l / CHROWS(512)

    long long zb  = (long long)tok * DIM_CONV;
    long long ob  = ((long long)(b*NCHUNK + chunk)) * DIM_CONV;
    long long gb  = (long long)tok * OUT_CPLX;
    long long qb  = (long long)tok * 768;

    if (tid < PK) {
        float den = g_z[zb + tid] + g_csum[ob + tid];
        s_inv[tid] = 1.f / fmaxf(den, 1e-4f);
    }
    __syncthreads();

    float hvals[OUT_CPLX/256];
    float sumsq = 0.f;
#pragma unroll
    for (int it = 0; it < OUT_CPLX/256; it++) {
        int f = tid + it*256;
        int k = f >> 7;
        int j = f & 127;
        int h = j & 63;
        int is_im = j >> 6;
        int idx = k*PH + h;

        float re_acc = g_z[zb + PK + idx]           + g_csum[ob + PK + idx];
        float im_acc = g_z[zb + PK + DIM_MEM + idx] + g_csum[ob + PK + DIM_MEM + idx];
        float sre = re_acc * s_inv[k];
        float sim = im_acc * s_inv[k];
        int kq = k >> 1;
        float qre = g_q[qb + (kq*PH + h)*2];
        float qim = g_q[qb + (kq*PH + h)*2 + 1];
        float val;
        if (!is_im) val = (sre*qre + sim*qim);
        else        val = (sim*qre - sre*qim);
        val *= 0.125f * g_wint[idx];

        float gv = g_gate[gb + f];
        float hv = val * (gv * sigmoidf_(gv));
        hvals[it] = hv;
        sumsq += hv*hv;
    }
#pragma unroll
    for (int o = 16; o > 0; o >>= 1) sumsq += __shfl_xor_sync(0xffffffff, sumsq, o);
    if ((tid & 31) == 0) s_red[tid >> 5] = sumsq;
    __syncthreads();
    if (tid < 32) {
        float v = (tid < 8) ? s_red[tid] : 0.f;
#pragma unroll
        for (int o = 4; o > 0; o >>= 1) v += __shfl_xor_sync(0xffffffff, v, o);
        if (tid == 0) s_red[0] = v;
    }
    __syncthreads();
    float rms = rsqrtf(s_red[0] / (float)OUT_CPLX + 1e-6f);

#pragma unroll
    for (int it = 0; it < OUT_CPLX/256; it++) {
        int f = tid + it*256;
        float v = hvals[it] * rms * gnw[f];
        __nv_bfloat16 h, lo;
        split2(v, h, lo);
        g_onh[gb + f] = h;
        g_onl[gb + f] = lo;
    }
}

// ---------------- launcher --------------------------
extern "C" void kernel_launch(void* const* d_in, const int* in_sizes, int n_in,
                              void* d_out, int out_size)
{
    const float* x        = (const float*)d_in[0];
    const float* W_in     = (const float*)d_in[1];
    const float* conv_w   = (const float*)d_in[2];
    const float* theta_raw= (const float*)d_in[3];
    const float* wint_raw = (const float*)d_in[4];
    const float* decay    = (const float*)d_in[5];
    const float* sscale   = (const float*)d_in[6];
    const float* sbias    = (const float*)d_in[7];
    const float* pscale   = (const float*)d_in[8];
    const float* gnw      = (const float*)d_in[9];
    const float* W_read   = (const float*)d_in[10];
    const float* W_gate   = (const float*)d_in[11];
    const float* W_out    = (const float*)d_in[12];
    float* out            = (float*)d_out;

    float *p_buf0, *p_gate;
    __nv_bfloat16 *p_xh, *p_xl, *p_Winh, *p_Winl, *p_Wgh, *p_Wgl;
    __nv_bfloat16 *p_Woh, *p_Wol, *p_Wrh, *p_Wrl, *p_onh, *p_onl, *p_yh, *p_yl;
    cudaGetSymbolAddress((void**)&p_buf0, g_buf0);
    cudaGetSymbolAddress((void**)&p_gate, g_gate);
    cudaGetSymbolAddress((void**)&p_xh,   g_xh);
    cudaGetSymbolAddress((void**)&p_xl,   g_xl);
    cudaGetSymbolAddress((void**)&p_Winh, g_Winh);
    cudaGetSymbolAddress((void**)&p_Winl, g_Winl);
    cudaGetSymbolAddress((void**)&p_Wgh,  g_Wgh);
    cudaGetSymbolAddress((void**)&p_Wgl,  g_Wgl);
    cudaGetSymbolAddress((void**)&p_Woh,  g_Woh);
    cudaGetSymbolAddress((void**)&p_Wol,  g_Wol);
    cudaGetSymbolAddress((void**)&p_Wrh,  g_Wrh);
    cudaGetSymbolAddress((void**)&p_Wrl,  g_Wrl);
    cudaGetSymbolAddress((void**)&p_onh,  g_onh);
    cudaGetSymbolAddress((void**)&p_onl,  g_onl);
    cudaGetSymbolAddress((void**)&p_yh,   g_yh);
    cudaGetSymbolAddress((void**)&p_yl,   g_yl);

    cudaFuncSetAttribute(gemm_mma_kernel,
                         cudaFuncAttributeMaxDynamicSharedMemorySize, GSMEM);

    // side stream + events for DAG-parallel sections (graph-capture fork/join)
    cudaStream_t s2;
    cudaStreamCreate(&s2);
    cudaEvent_t evFork, evJoin;
    cudaEventCreateWithFlags(&evFork, cudaEventDisableTiming);
    cudaEventCreateWithFlags(&evJoin, cudaEventDisableTiming);

    // 0) precompute + conversions needed by BOTH branches (stream 0)
    prep_kernel<<<1, 768>>>(theta_raw, wint_raw, decay);
    {
        size_t n = (size_t)NTOK * PD;
        split_x_kernel<<<(unsigned)((n + 255) / 256), 256>>>(x);
    }
    {
        dim3 blk(32, 8);
        tsplit_kernel<<<dim3((DIM_CONV+31)/32, PD/32),  blk>>>(W_in,  p_Winh, p_Winl, PD, DIM_CONV);
        tsplit_kernel<<<dim3(OUT_CPLX/32,      PD/32),  blk>>>(W_gate, p_Wgh, p_Wgl, PD, OUT_CPLX);
    }

    // ---- fork: side stream runs gate GEMM + later-needed weight prep ----
    cudaEventRecord(evFork, 0);
    cudaStreamWaitEvent(s2, evFork, 0);

    // side stream: W_out / W_read prep, then gate = x @ W_gate
    {
        dim3 blk(32, 8);
        tsplit_kernel<<<dim3(PD/32, 2304/32), blk, 0, s2>>>(W_out, p_Woh, p_Wol, 2304, PD);
    }
    tsplit_wr_kernel<<<(PK*128*384 + 255)/256, 256, 0, s2>>>(W_read);
    gemm_mma_kernel<<<dim3(OUT_CPLX/GBN, NTOK/GBM, 1), 256, GSMEM, s2>>>(
        NTOK, OUT_CPLX, PD, p_xh, p_xl, PD, 0, p_Wgh, p_Wgl, PD, 0,
        p_gate, OUT_CPLX, 0, nullptr, nullptr, 0);

    // stream 0: z_pre = x @ W_in, then conv/stack/scan
    gemm_mma_kernel<<<dim3((DIM_CONV + GBN - 1)/GBN, NTOK/GBM, 1), 256, GSMEM>>>(
        NTOK, DIM_CONV, PD, p_xh, p_xl, PD, 0, p_Winh, p_Winl, PD, 0,
        p_buf0, DIM_CONV, 0, nullptr, nullptr, 0);
    convstack_kernel<<<NTOK, 256>>>(conv_w, sscale, sbias, pscale);
    scan_partial_kernel<<<dim3((DIM_CONV+127)/128, NCHUNK, PB), 128>>>();
    scan_offsets_kernel<<<(PB*DIM_CONV+255)/256, 256>>>();

    // ---- join: epilogue needs gate + scan ----
    cudaEventRecord(evJoin, s2);
    cudaStreamWaitEvent(0, evJoin, 0);

    // 5) epilogue: out_flat + gated rmsnorm -> bf16 split
    epilogue1_kernel<<<NTOK, 256>>>(gnw);

    // 6) batched readout + fused gating (12 batches) -> g_yh/g_yl
    gemm_mma_kernel<<<dim3(384/GBN, NTOK/GBM, PK), 256, GSMEM>>>(
        NTOK, 384, 128,
        p_onh, p_onl, OUT_CPLX, 128,
        p_Wrh, p_Wrl, 128, (long long)384*128,
        nullptr, 0, 0, p_yh, p_yl, 1);

    // 7) final: out = y @ W_out
    gemm_mma_kernel<<<dim3(PD/GBN, NTOK/GBM, 1), 256, GSMEM>>>(
        NTOK, PD, PK*DIM_EXPAND, p_yh, p_yl, PK*DIM_EXPAND, 0,
        p_Woh, p_Wol, PK*DIM_EXPAND, 0, out, PD, 0, nullptr, nullptr, 0);

    cudaEventDestroy(evFork);
    cudaEventDestroy(evJoin);
    cudaStreamDestroy(s2);
}

// round 13
// speedup vs baseline: 1.1773x; 1.1004x over previous
#include <cuda_runtime.h>
#include <cuda_bf16.h>
#include <cuda_fp16.h>
#include <math.h>
#include <stdint.h>

// ---------------- problem constants ----------------
#define PK      12
#define PKQ     6
#define PH      64
#define PD      768
#define DIM_MEM 768
#define DIM_MEM_TOT 780
#define DIM_CONV 1548
#define OUT_CPLX 1536
#define DIM_EXPAND 192
#define PMAXLEN 4096
#define PKSIZE  4
#define PB      4
#define PL      4096
#define NTOK    (PB*PL)
#define NCHUNK  8
#define CHROWS  (PL/NCHUNK)   // 512
#define YDIM    (PK*DIM_EXPAND)  // 2304

// ---------------- device scratch -------------------
__device__ float g_buf0[(size_t)NTOK*DIM_CONV];   // z_pre (GEMM1 out)
__device__ float g_z   [(size_t)NTOK*DIM_CONV];   // stack -> cumsum
__device__ float g_q   [(size_t)NTOK*768];        // q channels
__device__ float g_gate[(size_t)NTOK*OUT_CPLX];
__device__ float g_csum[(size_t)PB*NCHUNK*DIM_CONV];
__device__ float g_theta[PK*PH];
__device__ float g_wint [PK*PH];
__device__ float g_slope[PK];

// bf16 split operands
__device__ __nv_bfloat16 g_xh[(size_t)NTOK*PD];
__device__ __nv_bfloat16 g_xl[(size_t)NTOK*PD];
__device__ __nv_bfloat16 g_Winh[(size_t)DIM_CONV*PD];
__device__ __nv_bfloat16 g_Winl[(size_t)DIM_CONV*PD];
__device__ __nv_bfloat16 g_Wgh[(size_t)OUT_CPLX*PD];
__device__ __nv_bfloat16 g_Wgl[(size_t)OUT_CPLX*PD];
__device__ __nv_bfloat16 g_Wrh[(size_t)PK*384*128];
__device__ __nv_bfloat16 g_Wrl[(size_t)PK*384*128];
__device__ __nv_bfloat16 g_onh[(size_t)NTOK*OUT_CPLX];
__device__ __nv_bfloat16 g_onl[(size_t)NTOK*OUT_CPLX];

// fp16 operands for final GEMM (2-pass path)
__device__ __half g_y16h[(size_t)NTOK*YDIM];
__device__ __half g_y16l[(size_t)NTOK*YDIM];
__device__ __half g_Wo16[(size_t)PD*YDIM];       // [768][2304] K-major

// ---------------- helpers --------------------------
__device__ __forceinline__ float sigmoidf_(float x){ return 1.f/(1.f+expf(-x)); }
__device__ __forceinline__ float softplusf_(float x){ return (x>20.f)? x : log1pf(expf(x)); }
__device__ __forceinline__ void split2(float v, __nv_bfloat16& h, __nv_bfloat16& l){
    h = __float2bfloat16(v);
    l = __float2bfloat16(v - __bfloat162float(h));
}
__device__ __forceinline__ void split2h(float v, __half& h, __half& l){
    h = __float2half_rn(v);
    l = __float2half_rn(v - __half2float(h));
}
__device__ __forceinline__ uint32_t smem_u32(const void* p){
    uint32_t a;
    asm("{ .reg .u64 t; cvta.to.shared.u64 t, %1; cvt.u32.u64 %0, t; }" : "=r"(a) : "l"(p));
    return a;
}
__device__ __forceinline__ void cp16(uint32_t dst, const void* src){
    asm volatile("cp.async.ca.shared.global [%0], [%1], 16;" :: "r"(dst), "l"(src));
}
template<int NG> __device__ __forceinline__ void cpwait(){
    asm volatile("cp.async.wait_group %0;" :: "n"(NG) : "memory");
}
__device__ __forceinline__ void cpcommit(){
    asm volatile("cp.async.commit_group;" ::: "memory");
}
__device__ __forceinline__ void mma16816(float* c, uint32_t a0, uint32_t a1, uint32_t a2, uint32_t a3,
                                         uint32_t b0, uint32_t b1){
    asm volatile(
        "mma.sync.aligned.m16n8k16.row.col.f32.bf16.bf16.f32 "
        "{%0,%1,%2,%3}, {%4,%5,%6,%7}, {%8,%9}, {%0,%1,%2,%3};"
        : "+f"(c[0]), "+f"(c[1]), "+f"(c[2]), "+f"(c[3])
        : "r"(a0), "r"(a1), "r"(a2), "r"(a3), "r"(b0), "r"(b1));
}
__device__ __forceinline__ void mma16816h(float* c, uint32_t a0, uint32_t a1, uint32_t a2, uint32_t a3,
                                          uint32_t b0, uint32_t b1){
    asm volatile(
        "mma.sync.aligned.m16n8k16.row.col.f32.f16.f16.f32 "
        "{%0,%1,%2,%3}, {%4,%5,%6,%7}, {%8,%9}, {%0,%1,%2,%3};"
        : "+f"(c[0]), "+f"(c[1]), "+f"(c[2]), "+f"(c[3])
        : "r"(a0), "r"(a1), "r"(a2), "r"(a3), "r"(b0), "r"(b1));
}
__device__ __forceinline__ void ldsm4(uint32_t& r0, uint32_t& r1, uint32_t& r2, uint32_t& r3, uint32_t addr){
    asm volatile("ldmatrix.sync.aligned.m8n8.x4.shared.b16 {%0,%1,%2,%3}, [%4];"
                 : "=r"(r0), "=r"(r1), "=r"(r2), "=r"(r3) : "r"(addr));
}

// ---------------- split HMMA GEMM -------------------
// MODE 0: bf16 3-pass, fp32 store.
// MODE 1: bf16 3-pass, gated fp16-split store (val/gate interleaved cols).
// MODE 2: fp16 2-pass (A split hi/lo, B single), fp32 store. 3 smem tiles.
#define GBM 128
#define GBN 128
#define GBK 32
#define SA  40
#define TILE_ELEMS (128*SA)
#define TILE_BYTES (TILE_ELEMS*2)
#define NSTAGE 3
#define GSMEM (NSTAGE*4*TILE_BYTES)

template<int MODE>
__global__ void __launch_bounds__(256, 1)
gemm_mma_kernel(int M, int N, int Kd,
                const void* Ah_, const void* Al_, long long lda, long long sAb,
                const void* Bh_, const void* Bl_, long long ldb, long long sBb,
                float* __restrict__ C, long long ldc, long long sCb,
                __half* __restrict__ Oh, __half* __restrict__ Ol)
{
    constexpr int NTILES = (MODE == 2) ? 3 : 4;
    constexpr uint32_t STB = NTILES * TILE_BYTES;

    extern __shared__ char smem[];
    const uint32_t smb = smem_u32(smem);
    const int tid = threadIdx.x;
    const int wid = tid >> 5;
    const int lid = tid & 31;
    const int g = lid >> 2;
    const int t = lid & 3;
    const int wm = (wid & 1) * 64;
    const int wn = (wid >> 1) * 32;

    const int zb = blockIdx.z;
    const char* pAh = (const char*)Ah_ + (long long)zb * sAb * 2;
    const char* pAl = (const char*)Al_ + (long long)zb * sAb * 2;
    const char* pBh = (const char*)Bh_ + (long long)zb * sBb * 2;
    const char* pBl = (const char*)Bl_ + (long long)zb * sBb * 2;

    const int tile_n = blockIdx.x * GBN;
    const int tile_m = blockIdx.y * GBM;
    const int nChunks = Kd / GBK;

    const int a_row  = (lid & 15);
    const int a_koff = (lid >> 4) << 3;
    const int b_row  = (lid & 7) + ((lid >> 4) << 3);
    const int b_koff = ((lid >> 3) & 1) << 3;

    float acc[4][4][4];
#pragma unroll
    for (int i = 0; i < 4; i++)
#pragma unroll
        for (int j = 0; j < 4; j++)
#pragma unroll
            for (int r = 0; r < 4; r++) acc[i][j][r] = 0.f;

    auto load_stage = [&](int stage, int k0){
        uint32_t sbase = smb + stage * STB;
#pragma unroll
        for (int it = 0; it < NTILES*2; it++) {
            int idx = tid + it * 256;
            int tile = idx >> 9;
            int r    = (idx >> 2) & 127;
            int seg  = idx & 3;
            uint32_t dst = sbase + tile * TILE_BYTES + r * (SA*2) + seg * 16;
            const char* src;
            if (tile == 0)      src = pAh + ((long long)(tile_m + r) * lda + k0 + seg*8) * 2;
            else if (tile == 1) src = pAl + ((long long)(tile_m + r) * lda + k0 + seg*8) * 2;
            else {
                int n = tile_n + r;
                if (n >= N) n = 0;
                src = (tile == 2 ? pBh : pBl) + ((long long)n * ldb + k0 + seg*8) * 2;
            }
            cp16(dst, src);
        }
        cpcommit();
    };

    auto compute = [&](int stage){
        const uint32_t sb = smb + stage * STB;
#pragma unroll
        for (int ks = 0; ks < GBK; ks += 16) {
            uint32_t bh[4][2], bl[4][2];
#pragma unroll
            for (int p = 0; p < 2; p++) {
                uint32_t addr = sb + 2*TILE_BYTES +
                    ((wn + p*16 + b_row) * SA + ks + b_koff) * 2;
                ldsm4(bh[2*p][0], bh[2*p][1], bh[2*p+1][0], bh[2*p+1][1], addr);
                if (MODE != 2) {
                    addr += TILE_BYTES;
                    ldsm4(bl[2*p][0], bl[2*p][1], bl[2*p+1][0], bl[2*p+1][1], addr);
                }
            }
#pragma unroll
            for (int mt = 0; mt < 4; mt++) {
                uint32_t ah[4], al[4];
                uint32_t addr = sb + ((wm + mt*16 + a_row) * SA + ks + a_koff) * 2;
                ldsm4(ah[0], ah[1], ah[2], ah[3], addr);
                ldsm4(al[0], al[1], al[2], al[3], addr + TILE_BYTES);
                if (MODE == 2) {
#pragma unroll
                    for (int nt = 0; nt < 4; nt++)
                        mma16816h(acc[mt][nt], ah[0], ah[1], ah[2], ah[3], bh[nt][0], bh[nt][1]);
#pragma unroll
                    for (int nt = 0; nt < 4; nt++)
                        mma16816h(acc[mt][nt], al[0], al[1], al[2], al[3], bh[nt][0], bh[nt][1]);
                } else {
#pragma unroll
                    for (int nt = 0; nt < 4; nt++)
                        mma16816(acc[mt][nt], ah[0], ah[1], ah[2], ah[3], bh[nt][0], bh[nt][1]);
#pragma unroll
                    for (int nt = 0; nt < 4; nt++)
                        mma16816(acc[mt][nt], al[0], al[1], al[2], al[3], bh[nt][0], bh[nt][1]);
#pragma unroll
                    for (int nt = 0; nt < 4; nt++)
                        mma16816(acc[mt][nt], ah[0], ah[1], ah[2], ah[3], bl[nt][0], bl[nt][1]);
                }
            }
        }
    };

    load_stage(0, 0);
    if (nChunks > 1) load_stage(1, GBK);
    for (int i = 0; i < nChunks; i++) {
        if (i == nChunks - 1) cpwait<0>(); else cpwait<1>();
        __syncthreads();
        if (i + 2 < nChunks) load_stage((i + 2) % NSTAGE, (i + 2) * GBK);
        compute(i % NSTAGE);
        // no trailing sync: 3-stage ring + top-of-loop barrier protects reuse
    }

    if (MODE != 1) {
        float* Cz = C + (long long)zb * sCb;
#pragma unroll
        for (int mt = 0; mt < 4; mt++) {
            int row0 = tile_m + wm + mt*16 + g;
#pragma unroll
            for (int nt = 0; nt < 4; nt++) {
                int col = tile_n + wn + nt*8 + 2*t;
                if (col < N) {
                    float* p0 = Cz + (long long)row0 * ldc + col;
                    float* p1 = Cz + (long long)(row0 + 8) * ldc + col;
                    p0[0] = acc[mt][nt][0]; p0[1] = acc[mt][nt][1];
                    p1[0] = acc[mt][nt][2]; p1[1] = acc[mt][nt][3];
                }
            }
        }
    } else {
        // interleaved val/gate pairs: even col = val, odd col = gate -> fp16 split y
        const long long ldo = YDIM;                    // 2304
        const long long ob = (long long)zb * DIM_EXPAND;
#pragma unroll
        for (int mt = 0; mt < 4; mt++) {
            int row0 = tile_m + wm + mt*16 + g;
#pragma unroll
            for (int nt = 0; nt < 4; nt++) {
                int col = tile_n + wn + nt*8 + 2*t;   // even
                int n_out = col >> 1;
                float r0 = acc[mt][nt][0] * sigmoidf_(acc[mt][nt][1]);
                float r1 = acc[mt][nt][2] * sigmoidf_(acc[mt][nt][3]);
                __half h0, l0, h1, l1;
                split2h(r0, h0, l0); split2h(r1, h1, l1);
                long long o0 = (long long)row0 * ldo + ob + n_out;
                long long o1 = (long long)(row0 + 8) * ldo + ob + n_out;
                Oh[o0] = h0; Ol[o0] = l0;
                Oh[o1] = h1; Ol[o1] = l1;
            }
        }
    }
}

// ---------------- conversion kernels ----------------
__global__ void split_x_kernel(const float* __restrict__ x)
{
    size_t i = (size_t)blockIdx.x * blockDim.x + threadIdx.x;
    if (i >= (size_t)NTOK * PD) return;
    split2(x[i], g_xh[i], g_xl[i]);
}

// W[K,N] -> out[N,K] hi/lo bf16 via 32x32 smem tile transpose
__global__ void tsplit_kernel(const float* __restrict__ W,
                              __nv_bfloat16* __restrict__ oh,
                              __nv_bfloat16* __restrict__ ol,
                              int K, int N)
{
    __shared__ float tile[32][33];
    int n0 = blockIdx.x * 32, k0 = blockIdx.y * 32;
    int tx = threadIdx.x, ty = threadIdx.y;
#pragma unroll
    for (int i = ty; i < 32; i += 8) {
        int n = n0 + tx;
        tile[i][tx] = (n < N) ? W[(size_t)(k0 + i) * N + n] : 0.f;
    }
    __syncthreads();
#pragma unroll
    for (int i = ty; i < 32; i += 8) {
        int n = n0 + i;
        if (n < N) {
            __nv_bfloat16 h, l;
            split2(tile[tx][i], h, l);
            size_t o = (size_t)n * K + k0 + tx;
            oh[o] = h; ol[o] = l;
        }
    }
}

// W[K,N] -> out[N,K] single fp16 (B operand of the 2-pass final GEMM)
__global__ void tsplit_h_kernel(const float* __restrict__ W,
                                __half* __restrict__ oh, int K, int N)
{
    __shared__ float tile[32][33];
    int n0 = blockIdx.x * 32, k0 = blockIdx.y * 32;
    int tx = threadIdx.x, ty = threadIdx.y;
#pragma unroll
    for (int i = ty; i < 32; i += 8) {
        int n = n0 + tx;
        tile[i][tx] = (n < N) ? W[(size_t)(k0 + i) * N + n] : 0.f;
    }
    __syncthreads();
#pragma unroll
    for (int i = ty; i < 32; i += 8) {
        int n = n0 + i;
        if (n < N)
            oh[(size_t)n * K + k0 + tx] = __float2half_rn(tile[tx][i]);
    }
}

// W_read[12][128][384] -> Wr[12][n'][128], n' = interleave(val j -> 2j, gate j -> 2j+1)
__global__ void tsplit_wr_kernel(const float* __restrict__ W)
{
    int i = blockIdx.x * blockDim.x + threadIdx.x;
    if (i >= PK * 128 * 384) return;
    int b = i / (128 * 384);
    int rem = i - b * 128 * 384;
    int f = rem / 384, n = rem - f * 384;
    int np = (n < DIM_EXPAND) ? (2*n) : (2*(n - DIM_EXPAND) + 1);
    __nv_bfloat16 h, l;
    split2(W[i], h, l);
    size_t o = (size_t)b * 384 * 128 + (size_t)np * 128 + f;
    g_Wrh[o] = h; g_Wrl[o] = l;
}

// ---------------- small precompute ------------------
__global__ void prep_kernel(const float* __restrict__ theta_raw,
                            const float* __restrict__ wint_raw,
                            const float* __restrict__ decay)
{
    int i = threadIdx.x;
    if (i < PK*PH) {
        g_theta[i] = 0.001f + 2.999f * sigmoidf_(theta_raw[i]);
        float e = expf(wint_raw[i]);
        g_wint[i] = e / (e + 1e-6f);
    }
    if (i < PK) g_slope[i] = softplusf_(decay[i]);
}

// ---------------- fused conv+silu+stack -------------
__global__ void convstack_kernel(const float* __restrict__ conv_w,
                                 const float* __restrict__ score_scale,
                                 const float* __restrict__ score_bias,
                                 const float* __restrict__ phase_scale)
{
    __shared__ float s_pw[PK];
    int tok = blockIdx.x;
    int tid = threadIdx.x;
    int l = tok & (PL-1);
    long long zb = (long long)tok * DIM_CONV;

    auto conv1 = [&](int c) -> float {
        float acc = 0.f;
#pragma unroll
        for (int tt = 0; tt < PKSIZE; tt++) {
            int dl = l + tt - (PKSIZE-1);
            if (dl >= 0)
                acc += g_buf0[zb + (long long)(tt - (PKSIZE-1)) * DIM_CONV + c]
                       * conv_w[tt*DIM_CONV + c];
        }
        return acc * sigmoidf_(acc);
    };

    if (tid < PK) {
        float s  = conv1(DIM_MEM + tid);
        float u  = score_scale[tid]*s + score_bias[tid];
        float sp = softplusf_(u);
        float tw = expf(-g_slope[tid] * (float)(PMAXLEN-1 - l));
        float p  = fminf(fmaxf(sp*tw, 1e-4f), 5000.f);
        s_pw[tid] = p;
        g_z[zb + tid] = p;
    }
    __syncthreads();

    for (int i = tid; i < DIM_MEM; i += blockDim.x) {
        int k = i >> 6;
        float kv = conv1(i);
        float ks = kv * phase_scale[k];
        float phi = ks / (1.f + fabsf(ks)) * g_theta[i];
        float sn, cs;
        sincosf(phi, &sn, &cs);
        float kvw = kv * s_pw[k];
        g_z[zb + PK + i]           = kvw * cs;
        g_z[zb + PK + DIM_MEM + i] = kvw * sn;
    }
    for (int i = tid; i < 768; i += blockDim.x) {
        g_q[(long long)tok * 768 + i] = conv1(DIM_MEM_TOT + i);
    }
}

// ---------------- chunked scan (over g_z) -----------
__global__ void scan_partial_kernel()
{
    int c = blockIdx.x * blockDim.x + threadIdx.x;
    if (c >= DIM_CONV) return;
    int chunk = blockIdx.y;
    int b = blockIdx.z;

    long long base = ((long long)(b*PL + chunk*CHROWS)) * DIM_CONV + c;
    float run = 0.f;
#pragma unroll 4
    for (int r = 0; r < CHROWS; r++) {
        long long p = base + (long long)r * DIM_CONV;
        run += g_z[p];
        g_z[p] = run;
    }
    g_csum[((long long)(b*NCHUNK + chunk))*DIM_CONV + c] = run;
}

__global__ void scan_offsets_kernel()
{
    int i = blockIdx.x * blockDim.x + threadIdx.x;
    if (i >= PB*DIM_CONV) return;
    int b = i / DIM_CONV;
    int c = i - b*DIM_CONV;
    float off = 0.f;
#pragma unroll
    for (int ch = 0; ch < NCHUNK; ch++) {
        long long idx = ((long long)(b*NCHUNK + ch))*DIM_CONV + c;
        float t = g_csum[idx];
        g_csum[idx] = off;
        off += t;
    }
}

// ---------------- epilogue 1 ------------------------
__global__ void epilogue1_kernel(const float* __restrict__ gnw)
{
    __shared__ float s_inv[PK];
    __shared__ float s_red[8];
    int tok = blockIdx.x;
    int tid = threadIdx.x;
    int l = tok & (PL-1);
    int b = tok >> 12;
    int chunk = l >> 9;

    long long zb  = (long long)tok * DIM_CONV;
    long long ob  = ((long long)(b*NCHUNK + chunk)) * DIM_CONV;
    long long gb  = (long long)tok * OUT_CPLX;
    long long qb  = (long long)tok * 768;

    if (tid < PK) {
        float den = g_z[zb + tid] + g_csum[ob + tid];
        s_inv[tid] = 1.f / fmaxf(den, 1e-4f);
    }
    __syncthreads();

    float hvals[OUT_CPLX/256];
    float sumsq = 0.f;
#pragma unroll
    for (int it = 0; it < OUT_CPLX/256; it++) {
        int f = tid + it*256;
        int k = f >> 7;
        int j = f & 127;
        int h = j & 63;
        int is_im = j >> 6;
        int idx = k*PH + h;

        float re_acc = g_z[zb + PK + idx]           + g_csum[ob + PK + idx];
        float im_acc = g_z[zb + PK + DIM_MEM + idx] + g_csum[ob + PK + DIM_MEM + idx];
        float sre = re_acc * s_inv[k];
        float sim = im_acc * s_inv[k];
        int kq = k >> 1;
        float qre = g_q[qb + (kq*PH + h)*2];
        float qim = g_q[qb + (kq*PH + h)*2 + 1];
        float val;
        if (!is_im) val = (sre*qre + sim*qim);
        else        val = (sim*qre - sre*qim);
        val *= 0.125f * g_wint[idx];

        float gv = g_gate[gb + f];
        float hv = val * (gv * sigmoidf_(gv));
        hvals[it] = hv;
        sumsq += hv*hv;
    }
#pragma unroll
    for (int o = 16; o > 0; o >>= 1) sumsq += __shfl_xor_sync(0xffffffff, sumsq, o);
    if ((tid & 31) == 0) s_red[tid >> 5] = sumsq;
    __syncthreads();
    if (tid < 32) {
        float v = (tid < 8) ? s_red[tid] : 0.f;
#pragma unroll
        for (int o = 4; o > 0; o >>= 1) v += __shfl_xor_sync(0xffffffff, v, o);
        if (tid == 0) s_red[0] = v;
    }
    __syncthreads();
    float rms = rsqrtf(s_red[0] / (float)OUT_CPLX + 1e-6f);

#pragma unroll
    for (int it = 0; it < OUT_CPLX/256; it++) {
        int f = tid + it*256;
        float v = hvals[it] * rms * gnw[f];
        __nv_bfloat16 h, lo;
        split2(v, h, lo);
        g_onh[gb + f] = h;
        g_onl[gb + f] = lo;
    }
}

// ---------------- launcher --------------------------
extern "C" void kernel_launch(void* const* d_in, const int* in_sizes, int n_in,
                              void* d_out, int out_size)
{
    const float* x        = (const float*)d_in[0];
    const float* W_in     = (const float*)d_in[1];
    const float* conv_w   = (const float*)d_in[2];
    const float* theta_raw= (const float*)d_in[3];
    const float* wint_raw = (const float*)d_in[4];
    const float* decay    = (const float*)d_in[5];
    const float* sscale   = (const float*)d_in[6];
    const float* sbias    = (const float*)d_in[7];
    const float* pscale   = (const float*)d_in[8];
    const float* gnw      = (const float*)d_in[9];
    const float* W_read   = (const float*)d_in[10];
    const float* W_gate   = (const float*)d_in[11];
    const float* W_out    = (const float*)d_in[12];
    float* out            = (float*)d_out;

    float *p_buf0, *p_gate;
    __nv_bfloat16 *p_xh, *p_xl, *p_Winh, *p_Winl, *p_Wgh, *p_Wgl;
    __nv_bfloat16 *p_Wrh, *p_Wrl, *p_onh, *p_onl;
    __half *p_y16h, *p_y16l, *p_Wo16;
    cudaGetSymbolAddress((void**)&p_buf0, g_buf0);
    cudaGetSymbolAddress((void**)&p_gate, g_gate);
    cudaGetSymbolAddress((void**)&p_xh,   g_xh);
    cudaGetSymbolAddress((void**)&p_xl,   g_xl);
    cudaGetSymbolAddress((void**)&p_Winh, g_Winh);
    cudaGetSymbolAddress((void**)&p_Winl, g_Winl);
    cudaGetSymbolAddress((void**)&p_Wgh,  g_Wgh);
    cudaGetSymbolAddress((void**)&p_Wgl,  g_Wgl);
    cudaGetSymbolAddress((void**)&p_Wrh,  g_Wrh);
    cudaGetSymbolAddress((void**)&p_Wrl,  g_Wrl);
    cudaGetSymbolAddress((void**)&p_onh,  g_onh);
    cudaGetSymbolAddress((void**)&p_onl,  g_onl);
    cudaGetSymbolAddress((void**)&p_y16h, g_y16h);
    cudaGetSymbolAddress((void**)&p_y16l, g_y16l);
    cudaGetSymbolAddress((void**)&p_Wo16, g_Wo16);

    cudaFuncSetAttribute(gemm_mma_kernel<0>,
                         cudaFuncAttributeMaxDynamicSharedMemorySize, GSMEM);
    cudaFuncSetAttribute(gemm_mma_kernel<1>,
                         cudaFuncAttributeMaxDynamicSharedMemorySize, GSMEM);
    cudaFuncSetAttribute(gemm_mma_kernel<2>,
                         cudaFuncAttributeMaxDynamicSharedMemorySize, GSMEM);

    // side stream + events for DAG-parallel sections (graph-capture fork/join)
    cudaStream_t s2;
    cudaStreamCreate(&s2);
    cudaEvent_t evFork, evJoin;
    cudaEventCreateWithFlags(&evFork, cudaEventDisableTiming);
    cudaEventCreateWithFlags(&evJoin, cudaEventDisableTiming);

    // 0) precompute + conversions needed by BOTH branches (stream 0)
    prep_kernel<<<1, 768>>>(theta_raw, wint_raw, decay);
    {
        size_t n = (size_t)NTOK * PD;
        split_x_kernel<<<(unsigned)((n + 255) / 256), 256>>>(x);
    }
    {
        dim3 blk(32, 8);
        tsplit_kernel<<<dim3((DIM_CONV+31)/32, PD/32),  blk>>>(W_in,  p_Winh, p_Winl, PD, DIM_CONV);
        tsplit_kernel<<<dim3(OUT_CPLX/32,      PD/32),  blk>>>(W_gate, p_Wgh, p_Wgl, PD, OUT_CPLX);
    }

    // ---- fork: side stream runs gate GEMM + later-needed weight prep ----
    cudaEventRecord(evFork, 0);
    cudaStreamWaitEvent(s2, evFork, 0);

    // side stream: W_out (fp16) / W_read prep, then gate = x @ W_gate
    {
        dim3 blk(32, 8);
        tsplit_h_kernel<<<dim3(PD/32, YDIM/32), blk, 0, s2>>>(W_out, p_Wo16, YDIM, PD);
    }
    tsplit_wr_kernel<<<(PK*128*384 + 255)/256, 256, 0, s2>>>(W_read);
    gemm_mma_kernel<0><<<dim3(OUT_CPLX/GBN, NTOK/GBM, 1), 256, GSMEM, s2>>>(
        NTOK, OUT_CPLX, PD, p_xh, p_xl, PD, 0, p_Wgh, p_Wgl, PD, 0,
        p_gate, OUT_CPLX, 0, nullptr, nullptr);

    // stream 0: z_pre = x @ W_in, then conv/stack/scan
    gemm_mma_kernel<0><<<dim3((DIM_CONV + GBN - 1)/GBN, NTOK/GBM, 1), 256, GSMEM>>>(
        NTOK, DIM_CONV, PD, p_xh, p_xl, PD, 0, p_Winh, p_Winl, PD, 0,
        p_buf0, DIM_CONV, 0, nullptr, nullptr);
    convstack_kernel<<<NTOK, 256>>>(conv_w, sscale, sbias, pscale);
    scan_partial_kernel<<<dim3((DIM_CONV+127)/128, NCHUNK, PB), 128>>>();
    scan_offsets_kernel<<<(PB*DIM_CONV+255)/256, 256>>>();

    // ---- join: epilogue needs gate + scan ----
    cudaEventRecord(evJoin, s2);
    cudaStreamWaitEvent(0, evJoin, 0);

    // 5) epilogue: out_flat + gated rmsnorm -> bf16 split
    epilogue1_kernel<<<NTOK, 256>>>(gnw);

    // 6) batched readout + fused gating (12 batches) -> fp16 split y
    gemm_mma_kernel<1><<<dim3(384/GBN, NTOK/GBM, PK), 256, GSMEM>>>(
        NTOK, 384, 128,
        p_onh, p_onl, OUT_CPLX, 128,
        p_Wrh, p_Wrl, 128, (long long)384*128,
        nullptr, 0, 0, p_y16h, p_y16l);

    // 7) final: out = y @ W_out  (fp16 2-pass: A = y hi/lo, B = Wo16)
    gemm_mma_kernel<2><<<dim3(PD/GBN, NTOK/GBM, 1), 256, GSMEM>>>(
        NTOK, PD, YDIM, p_y16h, p_y16l, YDIM, 0,
        p_Wo16, nullptr, YDIM, 0, out, PD, 0, nullptr, nullptr);

    cudaEventDestroy(evFork);
    cudaEventDestroy(evJoin);
    cudaStreamDestroy(s2);
}

// round 16
// speedup vs baseline: 1.2815x; 1.0886x over previous
#include <cuda_runtime.h>
#include <cuda_bf16.h>
#include <cuda_fp16.h>
#include <math.h>
#include <stdint.h>

// ---------------- problem constants ----------------
#define PK      12
#define PKQ     6
#define PH      64
#define PD      768
#define DIM_MEM 768
#define DIM_MEM_TOT 780
#define DIM_CONV 1548
#define OUT_CPLX 1536
#define DIM_EXPAND 192
#define PMAXLEN 4096
#define PKSIZE  4
#define PB      4
#define PL      4096
#define NTOK    (PB*PL)
#define NCHUNK  8
#define CHROWS  (PL/NCHUNK)   // 512
#define YDIM    (PK*DIM_EXPAND)  // 2304

// ---------------- device scratch -------------------
__device__ float g_buf0[(size_t)NTOK*DIM_CONV];   // z_pre (GEMM1 out)
__device__ float g_z   [(size_t)NTOK*DIM_CONV];   // stack -> cumsum
__device__ float g_q   [(size_t)NTOK*768];        // q channels
__device__ float g_gate[(size_t)NTOK*OUT_CPLX];
__device__ float g_csum[(size_t)PB*NCHUNK*DIM_CONV];
__device__ float g_theta[PK*PH];
__device__ float g_wint [PK*PH];
__device__ float g_slope[PK];

// bf16 split operands (GEMM1: precision-critical path)
__device__ __nv_bfloat16 g_xh[(size_t)NTOK*PD];
__device__ __nv_bfloat16 g_xl[(size_t)NTOK*PD];
__device__ __nv_bfloat16 g_Winh[(size_t)DIM_CONV*PD];
__device__ __nv_bfloat16 g_Winl[(size_t)DIM_CONV*PD];

// fp16 operands (gate / readout / final: 2-pass path)
__device__ __half g_x16h[(size_t)NTOK*PD];
__device__ __half g_x16l[(size_t)NTOK*PD];
__device__ __half g_Wg16[(size_t)OUT_CPLX*PD];
__device__ __half g_Wr16[(size_t)PK*384*128];
__device__ __half g_on16h[(size_t)NTOK*OUT_CPLX];
__device__ __half g_on16l[(size_t)NTOK*OUT_CPLX];
__device__ __half g_y16h[(size_t)NTOK*YDIM];
__device__ __half g_y16l[(size_t)NTOK*YDIM];
__device__ __half g_Wo16[(size_t)PD*YDIM];       // [768][2304] K-major

// ---------------- helpers --------------------------
__device__ __forceinline__ float sigmoidf_(float x){ return 1.f/(1.f+expf(-x)); }
__device__ __forceinline__ float softplusf_(float x){ return (x>20.f)? x : log1pf(expf(x)); }
__device__ __forceinline__ void split2(float v, __nv_bfloat16& h, __nv_bfloat16& l){
    h = __float2bfloat16(v);
    l = __float2bfloat16(v - __bfloat162float(h));
}
__device__ __forceinline__ void split2h(float v, __half& h, __half& l){
    h = __float2half_rn(v);
    l = __float2half_rn(v - __half2float(h));
}
__device__ __forceinline__ uint32_t smem_u32(const void* p){
    uint32_t a;
    asm("{ .reg .u64 t; cvta.to.shared.u64 t, %1; cvt.u32.u64 %0, t; }" : "=r"(a) : "l"(p));
    return a;
}
__device__ __forceinline__ void cp16(uint32_t dst, const void* src){
    asm volatile("cp.async.ca.shared.global [%0], [%1], 16;" :: "r"(dst), "l"(src));
}
template<int NG> __device__ __forceinline__ void cpwait(){
    asm volatile("cp.async.wait_group %0;" :: "n"(NG) : "memory");
}
__device__ __forceinline__ void cpcommit(){
    asm volatile("cp.async.commit_group;" ::: "memory");
}
__device__ __forceinline__ void mma16816(float* c, uint32_t a0, uint32_t a1, uint32_t a2, uint32_t a3,
                                         uint32_t b0, uint32_t b1){
    asm volatile(
        "mma.sync.aligned.m16n8k16.row.col.f32.bf16.bf16.f32 "
        "{%0,%1,%2,%3}, {%4,%5,%6,%7}, {%8,%9}, {%0,%1,%2,%3};"
        : "+f"(c[0]), "+f"(c[1]), "+f"(c[2]), "+f"(c[3])
        : "r"(a0), "r"(a1), "r"(a2), "r"(a3), "r"(b0), "r"(b1));
}
__device__ __forceinline__ void mma16816h(float* c, uint32_t a0, uint32_t a1, uint32_t a2, uint32_t a3,
                                          uint32_t b0, uint32_t b1){
    asm volatile(
        "mma.sync.aligned.m16n8k16.row.col.f32.f16.f16.f32 "
        "{%0,%1,%2,%3}, {%4,%5,%6,%7}, {%8,%9}, {%0,%1,%2,%3};"
        : "+f"(c[0]), "+f"(c[1]), "+f"(c[2]), "+f"(c[3])
        : "r"(a0), "r"(a1), "r"(a2), "r"(a3), "r"(b0), "r"(b1));
}
__device__ __forceinline__ void ldsm4(uint32_t& r0, uint32_t& r1, uint32_t& r2, uint32_t& r3, uint32_t addr){
    asm volatile("ldmatrix.sync.aligned.m8n8.x4.shared.b16 {%0,%1,%2,%3}, [%4];"
                 : "=r"(r0), "=r"(r1), "=r"(r2), "=r"(r3) : "r"(addr));
}

// ---------------- split HMMA GEMM -------------------
// MODE 0: bf16 3-pass, fp32 store.     (GEMM1)
// MODE 2: fp16 2-pass, fp32 store.     (gate, final)
// MODE 3: fp16 2-pass, gated fp16-split store (val/gate interleaved). (readout)
#define GBM 128
#define GBN 128
#define GBK 32
#define SA  40
#define TILE_ELEMS (128*SA)
#define TILE_BYTES (TILE_ELEMS*2)
#define NSTAGE 3
#define GSMEM (NSTAGE*4*TILE_BYTES)

template<int MODE>
__global__ void __launch_bounds__(256, 1)
gemm_mma_kernel(int M, int N, int Kd,
                const void* Ah_, const void* Al_, long long lda, long long sAb,
                const void* Bh_, const void* Bl_, long long ldb, long long sBb,
                float* __restrict__ C, long long ldc, long long sCb,
                __half* __restrict__ Oh, __half* __restrict__ Ol)
{
    constexpr bool FP16P = (MODE >= 2);
    constexpr int NTILES = FP16P ? 3 : 4;
    constexpr uint32_t STB = NTILES * TILE_BYTES;

    extern __shared__ char smem[];
    const uint32_t smb = smem_u32(smem);
    const int tid = threadIdx.x;
    const int wid = tid >> 5;
    const int lid = tid & 31;
    const int g = lid >> 2;
    const int t = lid & 3;
    const int wm = (wid & 1) * 64;
    const int wn = (wid >> 1) * 32;

    const int zb = blockIdx.z;
    const char* pAh = (const char*)Ah_ + (long long)zb * sAb * 2;
    const char* pAl = (const char*)Al_ + (long long)zb * sAb * 2;
    const char* pBh = (const char*)Bh_ + (long long)zb * sBb * 2;
    const char* pBl = (const char*)Bl_ + (long long)zb * sBb * 2;

    const int tile_n = blockIdx.x * GBN;
    const int tile_m = blockIdx.y * GBM;
    const int nChunks = Kd / GBK;

    const int a_row  = (lid & 15);
    const int a_koff = (lid >> 4) << 3;
    const int b_row  = (lid & 7) + ((lid >> 4) << 3);
    const int b_koff = ((lid >> 3) & 1) << 3;

    float acc[4][4][4];
#pragma unroll
    for (int i = 0; i < 4; i++)
#pragma unroll
        for (int j = 0; j < 4; j++)
#pragma unroll
            for (int r = 0; r < 4; r++) acc[i][j][r] = 0.f;

    auto load_stage = [&](int stage, int k0){
        uint32_t sbase = smb + stage * STB;
#pragma unroll
        for (int it = 0; it < NTILES*2; it++) {
            int idx = tid + it * 256;
            int tile = idx >> 9;
            int r    = (idx >> 2) & 127;
            int seg  = idx & 3;
            uint32_t dst = sbase + tile * TILE_BYTES + r * (SA*2) + seg * 16;
            const char* src;
            if (tile == 0)      src = pAh + ((long long)(tile_m + r) * lda + k0 + seg*8) * 2;
            else if (tile == 1) src = pAl + ((long long)(tile_m + r) * lda + k0 + seg*8) * 2;
            else {
                int n = tile_n + r;
                if (n >= N) n = 0;
                src = (tile == 2 ? pBh : pBl) + ((long long)n * ldb + k0 + seg*8) * 2;
            }
            cp16(dst, src);
        }
        cpcommit();
    };

    auto compute = [&](int stage){
        const uint32_t sb = smb + stage * STB;
#pragma unroll
        for (int ks = 0; ks < GBK; ks += 16) {
            uint32_t bh[4][2], bl[4][2];
#pragma unroll
            for (int p = 0; p < 2; p++) {
                uint32_t addr = sb + 2*TILE_BYTES +
                    ((wn + p*16 + b_row) * SA + ks + b_koff) * 2;
                ldsm4(bh[2*p][0], bh[2*p][1], bh[2*p+1][0], bh[2*p+1][1], addr);
                if (!FP16P) {
                    addr += TILE_BYTES;
                    ldsm4(bl[2*p][0], bl[2*p][1], bl[2*p+1][0], bl[2*p+1][1], addr);
                }
            }
#pragma unroll
            for (int mt = 0; mt < 4; mt++) {
                uint32_t ah[4], al[4];
                uint32_t addr = sb + ((wm + mt*16 + a_row) * SA + ks + a_koff) * 2;
                ldsm4(ah[0], ah[1], ah[2], ah[3], addr);
                ldsm4(al[0], al[1], al[2], al[3], addr + TILE_BYTES);
                if (FP16P) {
#pragma unroll
                    for (int nt = 0; nt < 4; nt++)
                        mma16816h(acc[mt][nt], ah[0], ah[1], ah[2], ah[3], bh[nt][0], bh[nt][1]);
#pragma unroll
                    for (int nt = 0; nt < 4; nt++)
                        mma16816h(acc[mt][nt], al[0], al[1], al[2], al[3], bh[nt][0], bh[nt][1]);
                } else {
#pragma unroll
                    for (int nt = 0; nt < 4; nt++)
                        mma16816(acc[mt][nt], ah[0], ah[1], ah[2], ah[3], bh[nt][0], bh[nt][1]);
#pragma unroll
                    for (int nt = 0; nt < 4; nt++)
                        mma16816(acc[mt][nt], al[0], al[1], al[2], al[3], bh[nt][0], bh[nt][1]);
#pragma unroll
                    for (int nt = 0; nt < 4; nt++)
                        mma16816(acc[mt][nt], ah[0], ah[1], ah[2], ah[3], bl[nt][0], bl[nt][1]);
                }
            }
        }
    };

    load_stage(0, 0);
    if (nChunks > 1) load_stage(1, GBK);
    for (int i = 0; i < nChunks; i++) {
        if (i == nChunks - 1) cpwait<0>(); else cpwait<1>();
        __syncthreads();
        if (i + 2 < nChunks) load_stage((i + 2) % NSTAGE, (i + 2) * GBK);
        compute(i % NSTAGE);
        // no trailing sync: 3-stage ring + top-of-loop barrier protects reuse
    }

    if (MODE != 3) {
        float* Cz = C + (long long)zb * sCb;
#pragma unroll
        for (int mt = 0; mt < 4; mt++) {
            int row0 = tile_m + wm + mt*16 + g;
#pragma unroll
            for (int nt = 0; nt < 4; nt++) {
                int col = tile_n + wn + nt*8 + 2*t;
                if (col < N) {
                    float* p0 = Cz + (long long)row0 * ldc + col;
                    float* p1 = Cz + (long long)(row0 + 8) * ldc + col;
                    p0[0] = acc[mt][nt][0]; p0[1] = acc[mt][nt][1];
                    p1[0] = acc[mt][nt][2]; p1[1] = acc[mt][nt][3];
                }
            }
        }
    } else {
        // interleaved val/gate pairs: even col = val, odd col = gate -> fp16 split y
        const long long ldo = YDIM;                    // 2304
        const long long ob = (long long)zb * DIM_EXPAND;
#pragma unroll
        for (int mt = 0; mt < 4; mt++) {
            int row0 = tile_m + wm + mt*16 + g;
#pragma unroll
            for (int nt = 0; nt < 4; nt++) {
                int col = tile_n + wn + nt*8 + 2*t;   // even
                int n_out = col >> 1;
                float r0 = acc[mt][nt][0] * sigmoidf_(acc[mt][nt][1]);
                float r1 = acc[mt][nt][2] * sigmoidf_(acc[mt][nt][3]);
                __half h0, l0, h1, l1;
                split2h(r0, h0, l0); split2h(r1, h1, l1);
                long long o0 = (long long)row0 * ldo + ob + n_out;
                long long o1 = (long long)(row0 + 8) * ldo + ob + n_out;
                Oh[o0] = h0; Ol[o0] = l0;
                Oh[o1] = h1; Ol[o1] = l1;
            }
        }
    }
}

// ---------------- conversion kernels ----------------
// x -> bf16 hi/lo (GEMM1) + fp16 hi/lo (gate GEMM)
__global__ void split_x_kernel(const float* __restrict__ x)
{
    size_t i = (size_t)blockIdx.x * blockDim.x + threadIdx.x;
    if (i >= (size_t)NTOK * PD) return;
    float v = x[i];
    split2(v, g_xh[i], g_xl[i]);
    split2h(v, g_x16h[i], g_x16l[i]);
}

// W[K,N] -> out[N,K] hi/lo bf16 via 32x32 smem tile transpose
__global__ void tsplit_kernel(const float* __restrict__ W,
                              __nv_bfloat16* __restrict__ oh,
                              __nv_bfloat16* __restrict__ ol,
                              int K, int N)
{
    __shared__ float tile[32][33];
    int n0 = blockIdx.x * 32, k0 = blockIdx.y * 32;
    int tx = threadIdx.x, ty = threadIdx.y;
#pragma unroll
    for (int i = ty; i < 32; i += 8) {
        int n = n0 + tx;
        tile[i][tx] = (n < N) ? W[(size_t)(k0 + i) * N + n] : 0.f;
    }
    __syncthreads();
#pragma unroll
    for (int i = ty; i < 32; i += 8) {
        int n = n0 + i;
        if (n < N) {
            __nv_bfloat16 h, l;
            split2(tile[tx][i], h, l);
            size_t o = (size_t)n * K + k0 + tx;
            oh[o] = h; ol[o] = l;
        }
    }
}

// W[K,N] -> out[N,K] single fp16
__global__ void tsplit_h_kernel(const float* __restrict__ W,
                                __half* __restrict__ oh, int K, int N)
{
    __shared__ float tile[32][33];
    int n0 = blockIdx.x * 32, k0 = blockIdx.y * 32;
    int tx = threadIdx.x, ty = threadIdx.y;
#pragma unroll
    for (int i = ty; i < 32; i += 8) {
        int n = n0 + tx;
        tile[i][tx] = (n < N) ? W[(size_t)(k0 + i) * N + n] : 0.f;
    }
    __syncthreads();
#pragma unroll
    for (int i = ty; i < 32; i += 8) {
        int n = n0 + i;
        if (n < N)
            oh[(size_t)n * K + k0 + tx] = __float2half_rn(tile[tx][i]);
    }
}

// W_read[12][128][384] -> Wr16[12][n'][128] single fp16, n' interleaved
__global__ void tsplit_wr_h_kernel(const float* __restrict__ W)
{
    int i = blockIdx.x * blockDim.x + threadIdx.x;
    if (i >= PK * 128 * 384) return;
    int b = i / (128 * 384);
    int rem = i - b * 128 * 384;
    int f = rem / 384, n = rem - f * 384;
    int np = (n < DIM_EXPAND) ? (2*n) : (2*(n - DIM_EXPAND) + 1);
    size_t o = (size_t)b * 384 * 128 + (size_t)np * 128 + f;
    g_Wr16[o] = __float2half_rn(W[i]);
}

// ---------------- small precompute ------------------
__global__ void prep_kernel(const float* __restrict__ theta_raw,
                            const float* __restrict__ wint_raw,
                            const float* __restrict__ decay)
{
    int i = threadIdx.x;
    if (i < PK*PH) {
        g_theta[i] = 0.001f + 2.999f * sigmoidf_(theta_raw[i]);
        float e = expf(wint_raw[i]);
        g_wint[i] = e / (e + 1e-6f);
    }
    if (i < PK) g_slope[i] = softplusf_(decay[i]);
}

// ---------------- fused conv+silu+stack -------------
__global__ void convstack_kernel(const float* __restrict__ conv_w,
                                 const float* __restrict__ score_scale,
                                 const float* __restrict__ score_bias,
                                 const float* __restrict__ phase_scale)
{
    __shared__ float s_pw[PK];
    int tok = blockIdx.x;
    int tid = threadIdx.x;
    int l = tok & (PL-1);
    long long zb = (long long)tok * DIM_CONV;

    auto conv1 = [&](int c) -> float {
        float acc = 0.f;
#pragma unroll
        for (int tt = 0; tt < PKSIZE; tt++) {
            int dl = l + tt - (PKSIZE-1);
            if (dl >= 0)
                acc += g_buf0[zb + (long long)(tt - (PKSIZE-1)) * DIM_CONV + c]
                       * conv_w[tt*DIM_CONV + c];
        }
        return acc * sigmoidf_(acc);
    };

    if (tid < PK) {
        float s  = conv1(DIM_MEM + tid);
        float u  = score_scale[tid]*s + score_bias[tid];
        float sp = softplusf_(u);
        float tw = expf(-g_slope[tid] * (float)(PMAXLEN-1 - l));
        float p  = fminf(fmaxf(sp*tw, 1e-4f), 5000.f);
        s_pw[tid] = p;
        g_z[zb + tid] = p;
    }
    __syncthreads();

    for (int i = tid; i < DIM_MEM; i += blockDim.x) {
        int k = i >> 6;
        float kv = conv1(i);
        float ks = kv * phase_scale[k];
        float phi = ks / (1.f + fabsf(ks)) * g_theta[i];
        float sn, cs;
        sincosf(phi, &sn, &cs);
        float kvw = kv * s_pw[k];
        g_z[zb + PK + i]           = kvw * cs;
        g_z[zb + PK + DIM_MEM + i] = kvw * sn;
    }
    for (int i = tid; i < 768; i += blockDim.x) {
        g_q[(long long)tok * 768 + i] = conv1(DIM_MEM_TOT + i);
    }
}

// ---------------- chunked scan (over g_z) -----------
__global__ void scan_partial_kernel()
{
    int c = blockIdx.x * blockDim.x + threadIdx.x;
    if (c >= DIM_CONV) return;
    int chunk = blockIdx.y;
    int b = blockIdx.z;

    long long base = ((long long)(b*PL + chunk*CHROWS)) * DIM_CONV + c;
    float run = 0.f;
#pragma unroll 4
    for (int r = 0; r < CHROWS; r++) {
        long long p = base + (long long)r * DIM_CONV;
        run += g_z[p];
        g_z[p] = run;
    }
    g_csum[((long long)(b*NCHUNK + chunk))*DIM_CONV + c] = run;
}

__global__ void scan_offsets_kernel()
{
    int i = blockIdx.x * blockDim.x + threadIdx.x;
    if (i >= PB*DIM_CONV) return;
    int b = i / DIM_CONV;
    int c = i - b*DIM_CONV;
    float off = 0.f;
#pragma unroll
    for (int ch = 0; ch < NCHUNK; ch++) {
        long long idx = ((long long)(b*NCHUNK + ch))*DIM_CONV + c;
        float t = g_csum[idx];
        g_csum[idx] = off;
        off += t;
    }
}

// ---------------- epilogue 1 (writes fp16 split) ----
__global__ void epilogue1_kernel(const float* __restrict__ gnw)
{
    __shared__ float s_inv[PK];
    __shared__ float s_red[8];
    int tok = blockIdx.x;
    int tid = threadIdx.x;
    int l = tok & (PL-1);
    int b = tok >> 12;
    int chunk = l >> 9;

    long long zb  = (long long)tok * DIM_CONV;
    long long ob  = ((long long)(b*NCHUNK + chunk)) * DIM_CONV;
    long long gb  = (long long)tok * OUT_CPLX;
    long long qb  = (long long)tok * 768;

    if (tid < PK) {
        float den = g_z[zb + tid] + g_csum[ob + tid];
        s_inv[tid] = 1.f / fmaxf(den, 1e-4f);
    }
    __syncthreads();

    float hvals[OUT_CPLX/256];
    float sumsq = 0.f;
#pragma unroll
    for (int it = 0; it < OUT_CPLX/256; it++) {
        int f = tid + it*256;
        int k = f >> 7;
        int j = f & 127;
        int h = j & 63;
        int is_im = j >> 6;
        int idx = k*PH + h;

        float re_acc = g_z[zb + PK + idx]           + g_csum[ob + PK + idx];
        float im_acc = g_z[zb + PK + DIM_MEM + idx] + g_csum[ob + PK + DIM_MEM + idx];
        float sre = re_acc * s_inv[k];
        float sim = im_acc * s_inv[k];
        int kq = k >> 1;
        float qre = g_q[qb + (kq*PH + h)*2];
        float qim = g_q[qb + (kq*PH + h)*2 + 1];
        float val;
        if (!is_im) val = (sre*qre + sim*qim);
        else        val = (sim*qre - sre*qim);
        val *= 0.125f * g_wint[idx];

        float gv = g_gate[gb + f];
        float hv = val * (gv * sigmoidf_(gv));
        hvals[it] = hv;
        sumsq += hv*hv;
    }
#pragma unroll
    for (int o = 16; o > 0; o >>= 1) sumsq += __shfl_xor_sync(0xffffffff, sumsq, o);
    if ((tid & 31) == 0) s_red[tid >> 5] = sumsq;
    __syncthreads();
    if (tid < 32) {
        float v = (tid < 8) ? s_red[tid] : 0.f;
#pragma unroll
        for (int o = 4; o > 0; o >>= 1) v += __shfl_xor_sync(0xffffffff, v, o);
        if (tid == 0) s_red[0] = v;
    }
    __syncthreads();
    float rms = rsqrtf(s_red[0] / (float)OUT_CPLX + 1e-6f);

#pragma unroll
    for (int it = 0; it < OUT_CPLX/256; it++) {
        int f = tid + it*256;
        float v = hvals[it] * rms * gnw[f];
        __half h, lo;
        split2h(v, h, lo);
        g_on16h[gb + f] = h;
        g_on16l[gb + f] = lo;
    }
}

// ---------------- launcher --------------------------
extern "C" void kernel_launch(void* const* d_in, const int* in_sizes, int n_in,
                              void* d_out, int out_size)
{
    const float* x        = (const float*)d_in[0];
    const float* W_in     = (const float*)d_in[1];
    const float* conv_w   = (const float*)d_in[2];
    const float* theta_raw= (const float*)d_in[3];
    const float* wint_raw = (const float*)d_in[4];
    const float* decay    = (const float*)d_in[5];
    const float* sscale   = (const float*)d_in[6];
    const float* sbias    = (const float*)d_in[7];
    const float* pscale   = (const float*)d_in[8];
    const float* gnw      = (const float*)d_in[9];
    const float* W_read   = (const float*)d_in[10];
    const float* W_gate   = (const float*)d_in[11];
    const float* W_out    = (const float*)d_in[12];
    float* out            = (float*)d_out;

    float *p_buf0, *p_gate;
    __nv_bfloat16 *p_xh, *p_xl, *p_Winh, *p_Winl;
    __half *p_x16h, *p_x16l, *p_Wg16, *p_Wr16, *p_on16h, *p_on16l;
    __half *p_y16h, *p_y16l, *p_Wo16;
    cudaGetSymbolAddress((void**)&p_buf0, g_buf0);
    cudaGetSymbolAddress((void**)&p_gate, g_gate);
    cudaGetSymbolAddress((void**)&p_xh,   g_xh);
    cudaGetSymbolAddress((void**)&p_xl,   g_xl);
    cudaGetSymbolAddress((void**)&p_Winh, g_Winh);
    cudaGetSymbolAddress((void**)&p_Winl, g_Winl);
    cudaGetSymbolAddress((void**)&p_x16h, g_x16h);
    cudaGetSymbolAddress((void**)&p_x16l, g_x16l);
    cudaGetSymbolAddress((void**)&p_Wg16, g_Wg16);
    cudaGetSymbolAddress((void**)&p_Wr16, g_Wr16);
    cudaGetSymbolAddress((void**)&p_on16h, g_on16h);
    cudaGetSymbolAddress((void**)&p_on16l, g_on16l);
    cudaGetSymbolAddress((void**)&p_y16h, g_y16h);
    cudaGetSymbolAddress((void**)&p_y16l, g_y16l);
    cudaGetSymbolAddress((void**)&p_Wo16, g_Wo16);

    cudaFuncSetAttribute(gemm_mma_kernel<0>,
                         cudaFuncAttributeMaxDynamicSharedMemorySize, GSMEM);
    cudaFuncSetAttribute(gemm_mma_kernel<2>,
                         cudaFuncAttributeMaxDynamicSharedMemorySize, GSMEM);
    cudaFuncSetAttribute(gemm_mma_kernel<3>,
                         cudaFuncAttributeMaxDynamicSharedMemorySize, GSMEM);

    // side stream + events for DAG-parallel sections (graph-capture fork/join)
    cudaStream_t s2;
    cudaStreamCreate(&s2);
    cudaEvent_t evFork, evJoin;
    cudaEventCreateWithFlags(&evFork, cudaEventDisableTiming);
    cudaEventCreateWithFlags(&evJoin, cudaEventDisableTiming);

    // 0) precompute + conversions needed by BOTH branches (stream 0)
    prep_kernel<<<1, 768>>>(theta_raw, wint_raw, decay);
    {
        size_t n = (size_t)NTOK * PD;
        split_x_kernel<<<(unsigned)((n + 255) / 256), 256>>>(x);
    }
    {
        dim3 blk(32, 8);
        tsplit_kernel<<<dim3((DIM_CONV+31)/32, PD/32),  blk>>>(W_in,  p_Winh, p_Winl, PD, DIM_CONV);
    }

    // ---- fork: side stream runs gate GEMM + later-needed weight prep ----
    cudaEventRecord(evFork, 0);
    cudaStreamWaitEvent(s2, evFork, 0);

    // side stream: fp16 weight prep, then gate = x @ W_gate (fp16 2-pass)
    {
        dim3 blk(32, 8);
        // W_gate is [PD=768, OUT_CPLX=1536] row-major: K=PD, N=OUT_CPLX
        tsplit_h_kernel<<<dim3(OUT_CPLX/32, PD/32), blk, 0, s2>>>(W_gate, p_Wg16, PD, OUT_CPLX);
        // W_out is [YDIM=2304, PD=768] row-major: K=YDIM, N=PD
        tsplit_h_kernel<<<dim3(PD/32, YDIM/32),     blk, 0, s2>>>(W_out,  p_Wo16, YDIM, PD);
    }
    tsplit_wr_h_kernel<<<(PK*128*384 + 255)/256, 256, 0, s2>>>(W_read);
    gemm_mma_kernel<2><<<dim3(OUT_CPLX/GBN, NTOK/GBM, 1), 256, GSMEM, s2>>>(
        NTOK, OUT_CPLX, PD, p_x16h, p_x16l, PD, 0, p_Wg16, nullptr, PD, 0,
        p_gate, OUT_CPLX, 0, nullptr, nullptr);

    // stream 0: z_pre = x @ W_in (bf16 3-pass), then conv/stack/scan
    gemm_mma_kernel<0><<<dim3((DIM_CONV + GBN - 1)/GBN, NTOK/GBM, 1), 256, GSMEM>>>(
        NTOK, DIM_CONV, PD, p_xh, p_xl, PD, 0, p_Winh, p_Winl, PD, 0,
        p_buf0, DIM_CONV, 0, nullptr, nullptr);
    convstack_kernel<<<NTOK, 256>>>(conv_w, sscale, sbias, pscale);
    scan_partial_kernel<<<dim3((DIM_CONV+127)/128, NCHUNK, PB), 128>>>();
    scan_offsets_kernel<<<(PB*DIM_CONV+255)/256, 256>>>();

    // ---- join: epilogue needs gate + scan ----
    cudaEventRecord(evJoin, s2);
    cudaStreamWaitEvent(0, evJoin, 0);

    // 5) epilogue: out_flat + gated rmsnorm -> fp16 split
    epilogue1_kernel<<<NTOK, 256>>>(gnw);

    // 6) batched readout + fused gating (fp16 2-pass, 12 batches) -> fp16 split y
    gemm_mma_kernel<3><<<dim3(384/GBN, NTOK/GBM, PK), 256, GSMEM>>>(
        NTOK, 384, 128,
        p_on16h, p_on16l, OUT_CPLX, 128,
        p_Wr16, nullptr, 128, (long long)384*128,
        nullptr, 0, 0, p_y16h, p_y16l);

    // 7) final: out = y @ W_out  (fp16 2-pass)
    gemm_mma_kernel<2><<<dim3(PD/GBN, NTOK/GBM, 1), 256, GSMEM>>>(
        NTOK, PD, YDIM, p_y16h, p_y16l, YDIM, 0,
        p_Wo16, nullptr, YDIM, 0, out, PD, 0, nullptr, nullptr);

    cudaEventDestroy(evFork);
    cudaEventDestroy(evJoin);
    cudaStreamDestroy(s2);
}